// round 7
// baseline (speedup 1.0000x reference)
#include <cuda_runtime.h>
#include <cuda_bf16.h>
#include <math.h>
#include <stdint.h>

#define BB 2
#define LL 4096
#define DD 1024
#define DI 2048
#define HH 16
#define HD 128
#define NN 128
#define CS 256
#define NC 16
#define MC 256
#define NM 16
#define PROJ 8208
#define BL 8192
#define ALPHA 0.5f

// ================= fp32 scratch =================
static __device__ __align__(256) float g_proj[(size_t)BL * PROJ];
static __device__ __align__(256) float g_val[(size_t)BL * DI];
static __device__ __align__(256) float g_cum[(size_t)BB * HH * NC * CS];
static __device__ __align__(256) float g_T[(size_t)BB * HH * NC * HD * NN];
static __device__ __align__(256) float g_hst[(size_t)BB * HH * NC * HD * NN];
static __device__ __align__(256) float g_out[(size_t)BL * DD];
static __device__ __align__(256) float g_v[(size_t)BL * DD];
static __device__ __align__(256) float g_U[(size_t)BB * NM * DD * DD];
static __device__ __align__(256) float g_reads[(size_t)BL * DD];

// ================= bf16 split scratch =================
static __device__ __align__(256) __nv_bfloat16 g_xnh[(size_t)BL * DD],    g_xnl[(size_t)BL * DD];
static __device__ __align__(256) __nv_bfloat16 g_winh[(size_t)PROJ * DD], g_winl[(size_t)PROJ * DD];
static __device__ __align__(256) __nv_bfloat16 g_Ygh[(size_t)BL * DI],    g_Ygl[(size_t)BL * DI];
static __device__ __align__(256) __nv_bfloat16 g_woh[(size_t)DD * DI],    g_wol[(size_t)DD * DI];
static __device__ __align__(256) __nv_bfloat16 g_outh[(size_t)BL * DD],   g_outl[(size_t)BL * DD];
static __device__ __align__(256) __nv_bfloat16 g_wwh[(size_t)DD * DD],    g_wwl[(size_t)DD * DD];
static __device__ __align__(256) __nv_bfloat16 g_wrh[(size_t)DD * DD],    g_wrl[(size_t)DD * DD];
static __device__ __align__(256) __nv_bfloat16 g_wkh[(size_t)BL * DD],    g_wkl[(size_t)BL * DD];
static __device__ __align__(256) __nv_bfloat16 g_wkTh[(size_t)BL * DD],   g_wkTl[(size_t)BL * DD];
static __device__ __align__(256) __nv_bfloat16 g_rkgh[(size_t)BL * DD],   g_rkgl[(size_t)BL * DD];
static __device__ __align__(256) __nv_bfloat16 g_vgwTh[(size_t)BL * DD],  g_vgwTl[(size_t)BL * DD];
static __device__ __align__(256) __nv_bfloat16 g_vTh[(size_t)BL * DD],    g_vTl[(size_t)BL * DD];
static __device__ __align__(256) __nv_bfloat16 g_Wsth[(size_t)BB * NM * DD * DD], g_Wstl[(size_t)BB * NM * DD * DD];
static __device__ __align__(256) __nv_bfloat16 g_Ph[(size_t)BB * NM * MC * MC],   g_Pl[(size_t)BB * NM * MC * MC];
static __device__ __align__(256) __nv_bfloat16 g_rdh[(size_t)BL * DD],    g_rdl[(size_t)BL * DD];

enum { EPI_STORE = 0, EPI_MASK_SPLIT = 1, EPI_ADD = 2, EPI_FINAL = 3, EPI_STORE_SPLIT = 4, EPI_ADD_SPLIT = 5 };

// ================= ptx helpers (all plain sm_80+ features) =================
__device__ __forceinline__ uint32_t smem_u32(const void* p) {
    uint32_t a;
    asm("{ .reg .u64 tmp; cvta.to.shared.u64 tmp, %1; cvt.u32.u64 %0, tmp; }" : "=r"(a) : "l"(p));
    return a;
}
__device__ __forceinline__ void cp16(uint32_t dst, const void* src, int ok) {
    int sz = ok ? 16 : 0;
    asm volatile("cp.async.cg.shared.global [%0], [%1], 16, %2;" :: "r"(dst), "l"(src), "r"(sz) : "memory");
}
#define CP_COMMIT() asm volatile("cp.async.commit_group;" ::: "memory")
#define CP_WAIT1()  asm volatile("cp.async.wait_group 1;" ::: "memory")
#define CP_WAIT0()  asm volatile("cp.async.wait_group 0;" ::: "memory")

#define LDM4(r, a) \
    asm volatile("ldmatrix.sync.aligned.m8n8.x4.shared.b16 {%0,%1,%2,%3}, [%4];" \
        : "=r"((r)[0]), "=r"((r)[1]), "=r"((r)[2]), "=r"((r)[3]) : "r"(a))
#define LDM2(r, a) \
    asm volatile("ldmatrix.sync.aligned.m8n8.x2.shared.b16 {%0,%1}, [%2];" \
        : "=r"((r)[0]), "=r"((r)[1]) : "r"(a))
#define MMA16816(c, a, b) \
    asm volatile("mma.sync.aligned.m16n8k16.row.col.f32.bf16.bf16.f32 " \
        "{%0,%1,%2,%3}, {%4,%5,%6,%7}, {%8,%9}, {%0,%1,%2,%3};" \
        : "+f"((c)[0]), "+f"((c)[1]), "+f"((c)[2]), "+f"((c)[3]) \
        : "r"((a)[0]), "r"((a)[1]), "r"((a)[2]), "r"((a)[3]), "r"((b)[0]), "r"((b)[1]))

__device__ __forceinline__ void split2(float v, __nv_bfloat16& h, __nv_bfloat16& l) {
    h = __float2bfloat16(v);
    l = __float2bfloat16(v - __bfloat162float(h));
}

// ================= mma.sync split-bf16 GEMM =================
// C[m,n] = sum_k A[m,k]*B[n,k], via Ahi*Bhi + Ahi*Blo + Alo*Bhi
// block tile 128x128, BK=32, 256 threads (8 warps, 2x4), warp tile 64x32.
// smem per stage: 4 tiles (Ah,Al,Bh,Bl), each 128 rows x 80B. 2-stage, 2 CTAs/SM.
#define TILE_B 10240
#define STAGE_B 40960
__global__ void __launch_bounds__(256, 2) tgemm_kernel(
    const __nv_bfloat16* __restrict__ Ahi, const __nv_bfloat16* __restrict__ Alo,
    const __nv_bfloat16* __restrict__ Bhi, const __nv_bfloat16* __restrict__ Blo,
    float* __restrict__ C, __nv_bfloat16* __restrict__ Chi, __nv_bfloat16* __restrict__ Clo,
    int N, int K, long lda, long ldb, long ldc,
    long bsa, long bsb, long bsc,
    int epi, const float* __restrict__ aux1, const float* __restrict__ aux2,
    const float* __restrict__ decayp, float alpha)
{
    extern __shared__ char smem[];
    uint32_t sbase = smem_u32(smem);
    int t = threadIdx.x, lane = t & 31, wid = t >> 5;
    int wm = wid >> 2, wn = wid & 3;

    int bz = blockIdx.z;
    Ahi += (long)bz * bsa; Alo += (long)bz * bsa;
    Bhi += (long)bz * bsb; Blo += (long)bz * bsb;
    long m0 = (long)blockIdx.y * 128, n0 = (long)blockIdx.x * 128;

    float acc[4][4][4];
#pragma unroll
    for (int mt = 0; mt < 4; mt++)
#pragma unroll
        for (int nt = 0; nt < 4; nt++)
#pragma unroll
            for (int e = 0; e < 4; e++) acc[mt][nt][e] = 0.f;

    int nk = K >> 5;  // K-chunks of 32

    auto load_stage = [&](int s, int ck) {
        long k0 = (long)ck * 32;
        uint32_t sb = sbase + s * STAGE_B;
#pragma unroll
        for (int i = 0; i < 8; i++) {
            int ch = t + i * 256;
            int tile = ch >> 9; int idx = ch & 511; int row = idx >> 2; int part = idx & 3;
            uint32_t dst = sb + tile * TILE_B + row * 80 + part * 16;
            const __nv_bfloat16* srcp;
            int ok = 1;
            if (tile == 0)      srcp = Ahi + (m0 + row) * lda + k0 + part * 8;
            else if (tile == 1) srcp = Alo + (m0 + row) * lda + k0 + part * 8;
            else {
                ok = (n0 + row) < N;
                long r = ok ? (n0 + row) : 0;
                srcp = ((tile == 2) ? Bhi : Blo) + r * ldb + k0 + part * 8;
            }
            cp16(dst, srcp, ok);
        }
        CP_COMMIT();
    };

    load_stage(0, 0);

    for (int ck = 0; ck < nk; ck++) {
        int s = ck & 1;
        if (ck + 1 < nk) { load_stage(s ^ 1, ck + 1); CP_WAIT1(); }
        else CP_WAIT0();
        __syncthreads();

        uint32_t sb = sbase + s * STAGE_B;
        uint32_t a_r = (uint32_t)(wm * 64 + (lane & 15));
        uint32_t a_kb = (uint32_t)((lane >> 4) * 16);
        uint32_t b_r = (uint32_t)(wn * 32 + (lane & 7));
        uint32_t b_kb = (uint32_t)(((lane >> 3) & 1) * 16);
#pragma unroll
        for (int ks = 0; ks < 2; ks++) {
            uint32_t kof = ks * 32;
            uint32_t bh[4][2], bl[4][2];
#pragma unroll
            for (int nt = 0; nt < 4; nt++) {
                uint32_t ab = sb + (b_r + nt * 8) * 80 + kof + b_kb;
                LDM2(bh[nt], ab + 2 * TILE_B);
                LDM2(bl[nt], ab + 3 * TILE_B);
            }
#pragma unroll
            for (int mt = 0; mt < 4; mt++) {
                uint32_t ah[4], al[4];
                uint32_t aa = sb + (a_r + mt * 16) * 80 + kof + a_kb;
                LDM4(ah, aa);
                LDM4(al, aa + TILE_B);
#pragma unroll
                for (int nt = 0; nt < 4; nt++) {
                    MMA16816(acc[mt][nt], ah, bh[nt]);
                    MMA16816(acc[mt][nt], ah, bl[nt]);
                    MMA16816(acc[mt][nt], al, bh[nt]);
                }
            }
        }
        __syncthreads();
    }

    // ---- epilogue ----
    float lg = 0.f;
    if (epi == EPI_MASK_SPLIT) {
        float gamma = 1.f / (1.f + expf(-decayp[0]));
        lg = logf(gamma);
    }
    C += (long)bz * bsc;
    if (Chi) { Chi += (long)bz * bsc; Clo += (long)bz * bsc; }

#pragma unroll
    for (int mt = 0; mt < 4; mt++) {
#pragma unroll
        for (int nt = 0; nt < 4; nt++) {
            long col = n0 + wn * 32 + nt * 8 + (lane & 3) * 2;
            long row0 = m0 + wm * 64 + mt * 16 + (lane >> 2);
#pragma unroll
            for (int e = 0; e < 4; e++) {
                long m = row0 + (e >> 1) * 8;
                long n = col + (e & 1);
                if (n >= N) continue;
                long idx = m * ldc + n;
                float v = acc[mt][nt][e];
                if (epi == EPI_STORE) C[idx] = v;
                else if (epi == EPI_STORE_SPLIT) {
                    C[idx] = v;
                    split2(v, Chi[idx], Clo[idx]);
                } else if (epi == EPI_MASK_SPLIT) {
                    float mv = (m > n) ? v * expf((float)(m - 1 - n) * lg) : 0.f;
                    split2(mv, Chi[idx], Clo[idx]);
                } else if (epi == EPI_ADD) C[idx] += v;
                else if (epi == EPI_ADD_SPLIT) {
                    float r = C[idx] + v;
                    C[idx] = r;
                    split2(r, Chi[idx], Clo[idx]);
                } else C[idx] = aux1[idx] + aux2[idx] + alpha * v;
            }
        }
    }
}

// ================= elementwise / SIMT kernels =================
__global__ void splitk_kernel(const float* __restrict__ src, __nv_bfloat16* __restrict__ h,
                              __nv_bfloat16* __restrict__ l, long n)
{
    long i = (long)blockIdx.x * 256 + threadIdx.x;
    if (i >= n) return;
    split2(src[i], h[i], l[i]);
}

__global__ void rmsnorm_kernel(const float* __restrict__ x, const float* __restrict__ w)
{
    int row = blockIdx.x;
    const float* xr = x + (long)row * DD;
    float s = 0.f;
    for (int i = threadIdx.x; i < DD; i += 256) { float v = xr[i]; s += v * v; }
    __shared__ float red[256];
    red[threadIdx.x] = s; __syncthreads();
    for (int o = 128; o > 0; o >>= 1) {
        if (threadIdx.x < o) red[threadIdx.x] += red[threadIdx.x + o];
        __syncthreads();
    }
    float r = rsqrtf(red[0] / (float)DD + 1e-6f);
    for (int i = threadIdx.x; i < DD; i += 256) {
        float v = xr[i] * r * w[i];
        long idx = (long)row * DD + i;
        split2(v, g_xnh[idx], g_xnl[idx]);
    }
}

__global__ void conv_silu_kernel(const float* __restrict__ cw, const float* __restrict__ cb)
{
    long idx = (long)blockIdx.x * 256 + threadIdx.x;
    if (idx >= (long)BL * DI) return;
    int c = (int)(idx % DI);
    long bl = idx / DI;
    int l = (int)(bl % LL);
    long b = bl / LL;
    float acc = cb[c];
#pragma unroll
    for (int k = 0; k < 4; k++) {
        int ls = l - 3 + k;
        if (ls >= 0) acc += cw[c * 4 + k] * g_proj[(b * LL + ls) * (long)PROJ + c];
    }
    g_val[idx] = acc / (1.f + expf(-acc));
}

__global__ void cum_kernel(const float* __restrict__ dt_bias, const float* __restrict__ A_log)
{
    int bid = blockIdx.x;
    int c = bid % NC; int h = (bid / NC) % HH; int b = bid / (NC * HH);
    int t = threadIdx.x;
    long row = (long)b * LL + c * CS + t;
    float x = g_proj[row * (long)PROJ + 2 * DI + 2 * HH * NN + h] + dt_bias[h];
    float sp = (x > 20.f) ? x : log1pf(expf(x));
    float ld = -expf(A_log[h]) * sp;
    __shared__ float s[256];
    s[t] = ld; __syncthreads();
    for (int o = 1; o < 256; o <<= 1) {
        float v = (t >= o) ? s[t - o] : 0.f;
        __syncthreads();
        s[t] += v;
        __syncthreads();
    }
    g_cum[(long)bid * CS + t] = s[t];
}

__global__ void __launch_bounds__(256) ssd_T_kernel()
{
    int bid = blockIdx.x;
    int c = bid % NC; int h = (bid / NC) % HH; int b = bid / (NC * HH);
    const float* cumc = g_cum + (long)bid * CS;
    __shared__ float vw[32][128];
    __shared__ float Bs[32][128];
    __shared__ float ew[CS];
    int t = threadIdx.x;
    float cl = cumc[CS - 1];
    for (int i = t; i < CS; i += 256) ew[i] = expf(cl - cumc[i]);
    __syncthreads();
    int tx = t & 15, ty = t >> 4;
    float acc[8][8];
#pragma unroll
    for (int r = 0; r < 8; r++)
#pragma unroll
        for (int cc = 0; cc < 8; cc++) acc[r][cc] = 0.f;
    long rowb = (long)b * LL + (long)c * CS;
    for (int k0 = 0; k0 < CS; k0 += 32) {
#pragma unroll
        for (int i = 0; i < 16; i++) {
            int e = t + i * 256; int kl = e >> 7; int j = e & 127;
            long row = rowb + k0 + kl;
            vw[kl][j] = g_val[row * (long)DI + h * HD + j] * ew[k0 + kl];
            Bs[kl][j] = g_proj[row * (long)PROJ + 2 * DI + h * NN + j];
        }
        __syncthreads();
#pragma unroll 8
        for (int kk = 0; kk < 32; kk++) {
            float a[8], bb[8];
#pragma unroll
            for (int r = 0; r < 8; r++) { a[r] = vw[kk][ty * 8 + r]; bb[r] = Bs[kk][tx * 8 + r]; }
#pragma unroll
            for (int r = 0; r < 8; r++)
#pragma unroll
                for (int cc = 0; cc < 8; cc++) acc[r][cc] += a[r] * bb[cc];
        }
        __syncthreads();
    }
    float* Tb = g_T + (long)bid * HD * NN;
#pragma unroll
    for (int r = 0; r < 8; r++)
#pragma unroll
        for (int cc = 0; cc < 8; cc++)
            Tb[(ty * 8 + r) * NN + tx * 8 + cc] = acc[r][cc];
}

__global__ void hscan_kernel()
{
    long i = (long)blockIdx.x * 256 + threadIdx.x;
    if (i >= (long)BB * HH * HD * NN) return;
    int dn = (int)(i % (HD * NN));
    long bh = i / (HD * NN);
    float hcur = 0.f;
    for (int c = 0; c < NC; c++) {
        long off = (bh * NC + c) * (long)(HD * NN) + dn;
        float Ac = expf(g_cum[(bh * NC + c) * CS + CS - 1]);
        g_hst[off] = hcur;
        hcur = Ac * hcur + g_T[off];
    }
}

__global__ void __launch_bounds__(256) ssd_Y_kernel(const float* __restrict__ Dskip)
{
    extern __shared__ float sm[];
    float* CsT = sm;
    float* buf = CsT + 128 * 65;
    float* Mt = buf + 8448;
    float* cumsh = Mt + 64 * 65;

    int bid = blockIdx.x;
    int lt = bid & 3;
    int bhc = bid >> 2;
    int c = bhc % NC; int bh = bhc / NC; int h = bh % HH; int b = bh / HH;
    int t = threadIdx.x, tx = t & 15, ty = t >> 4;
    const float* cumc = g_cum + (long)bhc * CS;
    for (int i = t; i < CS; i += 256) cumsh[i] = cumc[i];
    int l0 = lt * 64;
    long rowb = (long)b * LL + (long)c * CS;

#pragma unroll
    for (int i = 0; i < 32; i++) {
        int e = t + i * 256; int n = e & 127; int l = e >> 7;
        CsT[n * 65 + l] = g_proj[(rowb + l0 + l) * (long)PROJ + 2 * DI + HH * NN + h * NN + n];
    }
    __syncthreads();

    float acc[4][8];
#pragma unroll
    for (int r = 0; r < 4; r++)
#pragma unroll
        for (int cc = 0; cc < 8; cc++) acc[r][cc] = 0.f;

    for (int mt = 0; mt <= lt; mt++) {
        int m0 = mt * 64;
#pragma unroll
        for (int i = 0; i < 32; i++) {
            int e = t + i * 256; int n = e & 127; int m = e >> 7;
            buf[n * 65 + m] = g_proj[(rowb + m0 + m) * (long)PROJ + 2 * DI + h * NN + n];
        }
        __syncthreads();
        float am[4][4];
#pragma unroll
        for (int r = 0; r < 4; r++)
#pragma unroll
            for (int s = 0; s < 4; s++) am[r][s] = 0.f;
#pragma unroll 4
        for (int n = 0; n < 128; n++) {
            float a0[4], b0[4];
#pragma unroll
            for (int r = 0; r < 4; r++) { a0[r] = CsT[n * 65 + ty * 4 + r]; b0[r] = buf[n * 65 + tx * 4 + r]; }
#pragma unroll
            for (int r = 0; r < 4; r++)
#pragma unroll
                for (int s = 0; s < 4; s++) am[r][s] += a0[r] * b0[s];
        }
        __syncthreads();
#pragma unroll
        for (int r = 0; r < 4; r++)
#pragma unroll
            for (int s = 0; s < 4; s++) {
                int ll = ty * 4 + r, mm = tx * 4 + s;
                int gl = l0 + ll, gm = m0 + mm;
                Mt[ll * 65 + mm] = (gl >= gm) ? am[r][s] * expf(cumsh[gl] - cumsh[gm]) : 0.f;
            }
        __syncthreads();
#pragma unroll
        for (int i = 0; i < 32; i++) {
            int e = t + i * 256; int d = e & 127; int j = e >> 7;
            buf[j * 132 + d] = g_val[(rowb + m0 + j) * (long)DI + h * HD + d];
        }
        __syncthreads();
#pragma unroll 4
        for (int j = 0; j < 64; j++) {
            float a0[4], b0[8];
#pragma unroll
            for (int r = 0; r < 4; r++) a0[r] = Mt[(ty * 4 + r) * 65 + j];
#pragma unroll
            for (int cc = 0; cc < 8; cc++) b0[cc] = buf[j * 132 + tx * 8 + cc];
#pragma unroll
            for (int r = 0; r < 4; r++)
#pragma unroll
                for (int cc = 0; cc < 8; cc++) acc[r][cc] += a0[r] * b0[cc];
        }
        __syncthreads();
    }

    const float* hb = g_hst + (long)bhc * HD * NN;
    for (int nt = 0; nt < 8; nt++) {
        int n0 = nt * 16;
#pragma unroll
        for (int i = 0; i < 8; i++) {
            int e = t + i * 256; int j = e & 15; int d = e >> 4;
            buf[j * 132 + d] = hb[d * NN + n0 + j];
        }
        __syncthreads();
#pragma unroll
        for (int r = 0; r < 4; r++) {
            float el = expf(cumsh[l0 + ty * 4 + r]);
            float tmp[8];
#pragma unroll
            for (int cc = 0; cc < 8; cc++) tmp[cc] = 0.f;
#pragma unroll
            for (int j = 0; j < 16; j++) {
                float cv = CsT[(n0 + j) * 65 + ty * 4 + r];
#pragma unroll
                for (int cc = 0; cc < 8; cc++) tmp[cc] += cv * buf[j * 132 + tx * 8 + cc];
            }
#pragma unroll
            for (int cc = 0; cc < 8; cc++) acc[r][cc] += el * tmp[cc];
        }
        __syncthreads();
    }

#pragma unroll
    for (int r = 0; r < 4; r++) {
        int gl = l0 + ty * 4 + r;
        long grow = rowb + gl;
#pragma unroll
        for (int cc = 0; cc < 8; cc++) {
            int d = tx * 8 + cc;
            float vv = g_val[grow * (long)DI + h * HD + d];
            float y = acc[r][cc] + Dskip[h * HD + d] * vv;
            float g = g_proj[grow * (long)PROJ + DI + h * HD + d];
            float yo = y * g / (1.f + expf(-g));
            long idx = grow * (long)DI + h * HD + d;
            split2(yo, g_Ygh[idx], g_Ygl[idx]);
        }
    }
}

// fused memory-module prep: wk splits (+transposed), rkg splits, vgwT/vT splits
__global__ void memprep_kernel(const float* __restrict__ decayp)
{
    long i = (long)blockIdx.x * 256 + threadIdx.x;
    if (i >= (long)BL * DD) return;
    int d = (int)(i % DD);
    long bl = i / DD;
    int linb = (int)(bl % LL);
    long b = bl / LL;
    int tt = linb % MC, cz = linb / MC;
    float gamma = 1.f / (1.f + expf(-decayp[0]));
    float lg = logf(gamma);
    long dstT = (((long)b * NM + cz) * DD + d) * MC + tt;

    float wkv = (linb == 0) ? 0.f : g_out[i - DD];
    split2(wkv, g_wkh[i], g_wkl[i]);
    split2(wkv, g_wkTh[dstT], g_wkTl[dstT]);

    float rk = g_out[i] * expf((float)tt * lg);
    split2(rk, g_rkgh[i], g_rkgl[i]);

    float vv = g_v[i];
    split2(vv, g_vTh[dstT], g_vTl[dstT]);
    float vgw = vv * expf((float)(MC - 1 - tt) * lg);
    split2(vgw, g_vgwTh[dstT], g_vgwTl[dstT]);
}

__global__ void wscan_kernel(const float* __restrict__ decayp)
{
    long i = (long)blockIdx.x * 256 + threadIdx.x;
    if (i >= (long)BB * DD * DD) return;
    long de = i % ((long)DD * DD);
    long b = i / ((long)DD * DD);
    float gamma = 1.f / (1.f + expf(-decayp[0]));
    float gmc = expf(256.f * logf(gamma));
    float w = 0.f;
    for (int c = 0; c < NM; c++) {
        long off = (b * NM + c) * (long)(DD * DD) + de;
        split2(w, g_Wsth[off], g_Wstl[off]);
        w = gmc * w + g_U[off];
    }
}

// ================= host launcher =================
template <typename T>
static T* symaddr(const void* s)
{
    void* p = nullptr;
    cudaGetSymbolAddress(&p, s);
    return (T*)p;
}

extern "C" void kernel_launch(void* const* d_in, const int* in_sizes, int n_in,
                              void* d_out, int out_size)
{
    const float* x = (const float*)d_in[0];
    const float* norm_w = (const float*)d_in[1];
    const float* w_in = (const float*)d_in[2];
    const float* conv_w = (const float*)d_in[3];
    const float* conv_b = (const float*)d_in[4];
    const float* A_log = (const float*)d_in[5];
    const float* dt_bias = (const float*)d_in[6];
    const float* D_skip = (const float*)d_in[7];
    const float* w_out = (const float*)d_in[8];
    const float* w_write = (const float*)d_in[9];
    const float* w_read = (const float*)d_in[10];
    const float* decay = (const float*)d_in[11];
    float* out = (float*)d_out;

    typedef __nv_bfloat16 bf;
    float* p_proj  = symaddr<float>(g_proj);
    float* p_out   = symaddr<float>(g_out);
    float* p_v     = symaddr<float>(g_v);
    float* p_U     = symaddr<float>(g_U);
    float* p_reads = symaddr<float>(g_reads);
    bf *xnh = symaddr<bf>(g_xnh),   *xnl = symaddr<bf>(g_xnl);
    bf *winh = symaddr<bf>(g_winh), *winl = symaddr<bf>(g_winl);
    bf *Ygh = symaddr<bf>(g_Ygh),   *Ygl = symaddr<bf>(g_Ygl);
    bf *woh = symaddr<bf>(g_woh),   *wol = symaddr<bf>(g_wol);
    bf *outh = symaddr<bf>(g_outh), *outl = symaddr<bf>(g_outl);
    bf *wwh = symaddr<bf>(g_wwh),   *wwl = symaddr<bf>(g_wwl);
    bf *wrh = symaddr<bf>(g_wrh),   *wrl = symaddr<bf>(g_wrl);
    bf *wkh = symaddr<bf>(g_wkh),   *wkl = symaddr<bf>(g_wkl);
    bf *wkTh = symaddr<bf>(g_wkTh), *wkTl = symaddr<bf>(g_wkTl);
    bf *rkgh = symaddr<bf>(g_rkgh), *rkgl = symaddr<bf>(g_rkgl);
    bf *vgwTh = symaddr<bf>(g_vgwTh), *vgwTl = symaddr<bf>(g_vgwTl);
    bf *vTh = symaddr<bf>(g_vTh),   *vTl = symaddr<bf>(g_vTl);
    bf *Wsth = symaddr<bf>(g_Wsth), *Wstl = symaddr<bf>(g_Wstl);
    bf *Phh = symaddr<bf>(g_Ph),    *Pll = symaddr<bf>(g_Pl);
    bf *rdh = symaddr<bf>(g_rdh),   *rdl = symaddr<bf>(g_rdl);

    const int gsmem = 2 * STAGE_B;  // 81920 -> 2 CTAs/SM
    cudaFuncSetAttribute(tgemm_kernel, cudaFuncAttributeMaxDynamicSharedMemorySize, gsmem);
    const int ysmem = (128 * 65 + 8448 + 64 * 65 + 256) * 4;
    cudaFuncSetAttribute(ssd_Y_kernel, cudaFuncAttributeMaxDynamicSharedMemorySize, ysmem);

    // weight splits
    splitk_kernel<<<(int)(((long)PROJ * DD + 255) / 256), 256>>>(w_in, winh, winl, (long)PROJ * DD);
    splitk_kernel<<<(int)(((long)DD * DI + 255) / 256), 256>>>(w_out, woh, wol, (long)DD * DI);
    splitk_kernel<<<(int)(((long)DD * DD + 255) / 256), 256>>>(w_write, wwh, wwl, (long)DD * DD);
    splitk_kernel<<<(int)(((long)DD * DD + 255) / 256), 256>>>(w_read, wrh, wrl, (long)DD * DD);

    rmsnorm_kernel<<<BL, 256>>>(x, norm_w);

    // proj = xn @ w_in^T  [8192 x 8208 x 1024]
    tgemm_kernel<<<dim3((PROJ + 127) / 128, BL / 128, 1), 256, gsmem>>>(
        xnh, xnl, winh, winl, p_proj, nullptr, nullptr,
        PROJ, DD, DD, DD, PROJ, 0, 0, 0, EPI_STORE, nullptr, nullptr, nullptr, 0.f);

    conv_silu_kernel<<<(int)(((long)BL * DI + 255) / 256), 256>>>(conv_w, conv_b);
    cum_kernel<<<BB * HH * NC, 256>>>(dt_bias, A_log);
    ssd_T_kernel<<<BB * HH * NC, 256>>>();
    hscan_kernel<<<(int)(((long)BB * HH * HD * NN + 255) / 256), 256>>>();
    ssd_Y_kernel<<<BB * HH * NC * 4, 256, ysmem>>>(D_skip);

    // out = Yg @ w_out^T  (store fp32 + splits)
    tgemm_kernel<<<dim3(DD / 128, BL / 128, 1), 256, gsmem>>>(
        Ygh, Ygl, woh, wol, p_out, outh, outl,
        DD, DI, DI, DI, DD, 0, 0, 0, EPI_STORE_SPLIT, nullptr, nullptr, nullptr, 0.f);

    // v = out @ w_write^T
    tgemm_kernel<<<dim3(DD / 128, BL / 128, 1), 256, gsmem>>>(
        outh, outl, wwh, wwl, p_v, nullptr, nullptr,
        DD, DD, DD, DD, DD, 0, 0, 0, EPI_STORE, nullptr, nullptr, nullptr, 0.f);

    // fused prep: wk (+T), rkg, vT, vgwT splits
    memprep_kernel<<<(int)(((long)BL * DD + 255) / 256), 256>>>(decay);

    // U[b,c,d,e] = sum_t vgwT[d,t]*wkT[e,t]
    tgemm_kernel<<<dim3(DD / 128, DD / 128, BB * NM), 256, gsmem>>>(
        vgwTh, vgwTl, wkTh, wkTl, p_U, nullptr, nullptr,
        DD, MC, MC, MC, DD,
        (long)DD * MC, (long)DD * MC, (long)DD * DD,
        EPI_STORE, nullptr, nullptr, nullptr, 0.f);

    wscan_kernel<<<(int)(((long)BB * DD * DD + 255) / 256), 256>>>(decay);

    // inter: reads = rkg @ Wst^T
    tgemm_kernel<<<dim3(DD / 128, MC / 128, BB * NM), 256, gsmem>>>(
        rkgh, rkgl, Wsth, Wstl, p_reads, nullptr, nullptr,
        DD, DD, DD, DD, DD,
        (long)MC * DD, (long)DD * DD, (long)MC * DD,
        EPI_STORE, nullptr, nullptr, nullptr, 0.f);

    // P = (out @ wk^T) * Mmem  -> split
    tgemm_kernel<<<dim3(MC / 128, MC / 128, BB * NM), 256, gsmem>>>(
        outh, outl, wkh, wkl, p_reads /*unused*/, Phh, Pll,
        MC, DD, DD, DD, MC,
        (long)MC * DD, (long)MC * DD, (long)MC * MC,
        EPI_MASK_SPLIT, nullptr, nullptr, decay, 0.f);

    // reads += P @ v  (B = vT), emit split of result
    tgemm_kernel<<<dim3(DD / 128, MC / 128, BB * NM), 256, gsmem>>>(
        Phh, Pll, vTh, vTl, p_reads, rdh, rdl,
        DD, MC, MC, MC, DD,
        (long)MC * MC, (long)DD * MC, (long)MC * DD,
        EPI_ADD_SPLIT, nullptr, nullptr, nullptr, 0.f);

    // final = x + out + 0.5 * reads @ w_read^T
    tgemm_kernel<<<dim3(DD / 128, BL / 128, 1), 256, gsmem>>>(
        rdh, rdl, wrh, wrl, out, nullptr, nullptr,
        DD, DD, DD, DD, DD, 0, 0, 0,
        EPI_FINAL, x, p_out, nullptr, ALPHA);
}

// round 9
// speedup vs baseline: 1.4128x; 1.4128x over previous
#include <cuda_runtime.h>
#include <cuda_bf16.h>
#include <math.h>
#include <stdint.h>

#define BB 2
#define LL 4096
#define DD 1024
#define DI 2048
#define HH 16
#define HD 128
#define NN 128
#define CS 256
#define NC 16
#define MC 256
#define NM 16
#define PROJ 8208
#define BL 8192
#define ALPHA 0.5f

// ================= fp32 scratch =================
static __device__ __align__(256) float g_proj[(size_t)BL * PROJ];
static __device__ __align__(256) float g_val[(size_t)BL * DI];
static __device__ __align__(256) float g_cum[(size_t)BB * HH * NC * CS];
static __device__ __align__(256) float g_T[(size_t)BB * HH * NC * HD * NN];
static __device__ __align__(256) float g_hst[(size_t)BB * HH * NC * HD * NN];
static __device__ __align__(256) float g_out[(size_t)BL * DD];
static __device__ __align__(256) float g_v[(size_t)BL * DD];
static __device__ __align__(256) float g_U[(size_t)BB * NM * DD * DD];
static __device__ __align__(256) float g_reads[(size_t)BL * DD];

// ================= bf16 split scratch =================
static __device__ __align__(256) __nv_bfloat16 g_xnh[(size_t)BL * DD],    g_xnl[(size_t)BL * DD];
static __device__ __align__(256) __nv_bfloat16 g_winh[(size_t)PROJ * DD], g_winl[(size_t)PROJ * DD];
static __device__ __align__(256) __nv_bfloat16 g_Ygh[(size_t)BL * DI],    g_Ygl[(size_t)BL * DI];
static __device__ __align__(256) __nv_bfloat16 g_woh[(size_t)DD * DI],    g_wol[(size_t)DD * DI];
static __device__ __align__(256) __nv_bfloat16 g_outh[(size_t)BL * DD],   g_outl[(size_t)BL * DD];
static __device__ __align__(256) __nv_bfloat16 g_wwh[(size_t)DD * DD],    g_wwl[(size_t)DD * DD];
static __device__ __align__(256) __nv_bfloat16 g_wrh[(size_t)DD * DD],    g_wrl[(size_t)DD * DD];
static __device__ __align__(256) __nv_bfloat16 g_wkh[(size_t)BL * DD],    g_wkl[(size_t)BL * DD];
static __device__ __align__(256) __nv_bfloat16 g_wkTh[(size_t)BL * DD],   g_wkTl[(size_t)BL * DD];
static __device__ __align__(256) __nv_bfloat16 g_rkgh[(size_t)BL * DD],   g_rkgl[(size_t)BL * DD];
static __device__ __align__(256) __nv_bfloat16 g_vgwTh[(size_t)BL * DD],  g_vgwTl[(size_t)BL * DD];
static __device__ __align__(256) __nv_bfloat16 g_vTh[(size_t)BL * DD],    g_vTl[(size_t)BL * DD];
static __device__ __align__(256) __nv_bfloat16 g_Wsth[(size_t)BB * NM * DD * DD], g_Wstl[(size_t)BB * NM * DD * DD];
static __device__ __align__(256) __nv_bfloat16 g_Ph[(size_t)BB * NM * MC * MC],   g_Pl[(size_t)BB * NM * MC * MC];
static __device__ __align__(256) __nv_bfloat16 g_rdh[(size_t)BL * DD],    g_rdl[(size_t)BL * DD];

enum { EPI_STORE = 0, EPI_MASK_SPLIT = 1, EPI_ADD = 2, EPI_FINAL = 3, EPI_STORE_SPLIT = 4, EPI_ADD_SPLIT = 5 };

// ================= ptx helpers (all plain sm_80+ features) =================
__device__ __forceinline__ uint32_t smem_u32(const void* p) {
    uint32_t a;
    asm("{ .reg .u64 tmp; cvta.to.shared.u64 tmp, %1; cvt.u32.u64 %0, tmp; }" : "=r"(a) : "l"(p));
    return a;
}
__device__ __forceinline__ void cp16(uint32_t dst, const void* src, int ok) {
    int sz = ok ? 16 : 0;
    asm volatile("cp.async.cg.shared.global [%0], [%1], 16, %2;" :: "r"(dst), "l"(src), "r"(sz) : "memory");
}
#define CP_COMMIT() asm volatile("cp.async.commit_group;" ::: "memory")
#define CP_WAIT1()  asm volatile("cp.async.wait_group 1;" ::: "memory")
#define CP_WAIT0()  asm volatile("cp.async.wait_group 0;" ::: "memory")

#define LDM4(r, a) \
    asm volatile("ldmatrix.sync.aligned.m8n8.x4.shared.b16 {%0,%1,%2,%3}, [%4];" \
        : "=r"((r)[0]), "=r"((r)[1]), "=r"((r)[2]), "=r"((r)[3]) : "r"(a))
#define LDM2(r, a) \
    asm volatile("ldmatrix.sync.aligned.m8n8.x2.shared.b16 {%0,%1}, [%2];" \
        : "=r"((r)[0]), "=r"((r)[1]) : "r"(a))
#define MMA16816(c, a, b) \
    asm volatile("mma.sync.aligned.m16n8k16.row.col.f32.bf16.bf16.f32 " \
        "{%0,%1,%2,%3}, {%4,%5,%6,%7}, {%8,%9}, {%0,%1,%2,%3};" \
        : "+f"((c)[0]), "+f"((c)[1]), "+f"((c)[2]), "+f"((c)[3]) \
        : "r"((a)[0]), "r"((a)[1]), "r"((a)[2]), "r"((a)[3]), "r"((b)[0]), "r"((b)[1]))

__device__ __forceinline__ void split2(float v, __nv_bfloat16& h, __nv_bfloat16& l) {
    h = __float2bfloat16(v);
    l = __float2bfloat16(v - __bfloat162float(h));
}

// ================= mma.sync split-bf16 GEMM =================
// C[m,n] = sum_k A[m,k]*B[n,k], via Ahi*Bhi + Ahi*Blo + Alo*Bhi
// block tile 128x128, BK=32, 256 threads (8 warps, 2x4), warp tile 64x32.
// smem per stage: 4 tiles (Ah,Al,Bh,Bl), each 128 rows x 80B. 2-stage.
#define TILE_B 10240
#define STAGE_B 40960
__global__ void __launch_bounds__(256) tgemm_kernel(
    const __nv_bfloat16* __restrict__ Ahi, const __nv_bfloat16* __restrict__ Alo,
    const __nv_bfloat16* __restrict__ Bhi, const __nv_bfloat16* __restrict__ Blo,
    float* __restrict__ C, __nv_bfloat16* __restrict__ Chi, __nv_bfloat16* __restrict__ Clo,
    int N, int K, long lda, long ldb, long ldc,
    long bsa, long bsb, long bsc,
    int epi, const float* __restrict__ aux1, const float* __restrict__ aux2,
    const float* __restrict__ decayp, float alpha)
{
    extern __shared__ char smem[];
    uint32_t sbase = smem_u32(smem);
    int t = threadIdx.x, lane = t & 31, wid = t >> 5;
    int wm = wid >> 2, wn = wid & 3;

    int bz = blockIdx.z;
    Ahi += (long)bz * bsa; Alo += (long)bz * bsa;
    Bhi += (long)bz * bsb; Blo += (long)bz * bsb;
    long m0 = (long)blockIdx.y * 128, n0 = (long)blockIdx.x * 128;

    float acc[4][4][4];
#pragma unroll
    for (int mt = 0; mt < 4; mt++)
#pragma unroll
        for (int nt = 0; nt < 4; nt++)
#pragma unroll
            for (int e = 0; e < 4; e++) acc[mt][nt][e] = 0.f;

    int nk = K >> 5;  // K-chunks of 32

    auto load_stage = [&](int s, int ck) {
        long k0 = (long)ck * 32;
        uint32_t sb = sbase + s * STAGE_B;
#pragma unroll
        for (int i = 0; i < 8; i++) {
            int ch = t + i * 256;
            int tile = ch >> 9; int idx = ch & 511; int row = idx >> 2; int part = idx & 3;
            uint32_t dst = sb + tile * TILE_B + row * 80 + part * 16;
            const __nv_bfloat16* srcp;
            int ok = 1;
            if (tile == 0)      srcp = Ahi + (m0 + row) * lda + k0 + part * 8;
            else if (tile == 1) srcp = Alo + (m0 + row) * lda + k0 + part * 8;
            else {
                ok = (n0 + row) < N;
                long r = ok ? (n0 + row) : 0;
                srcp = ((tile == 2) ? Bhi : Blo) + r * ldb + k0 + part * 8;
            }
            cp16(dst, srcp, ok);
        }
        CP_COMMIT();
    };

    load_stage(0, 0);

    for (int ck = 0; ck < nk; ck++) {
        int s = ck & 1;
        if (ck + 1 < nk) { load_stage(s ^ 1, ck + 1); CP_WAIT1(); }
        else CP_WAIT0();
        __syncthreads();

        uint32_t sb = sbase + s * STAGE_B;
        uint32_t a_r = (uint32_t)(wm * 64 + (lane & 15));
        uint32_t a_kb = (uint32_t)((lane >> 4) * 16);
        uint32_t b_r = (uint32_t)(wn * 32 + (lane & 7));
        uint32_t b_kb = (uint32_t)(((lane >> 3) & 1) * 16);
#pragma unroll
        for (int ks = 0; ks < 2; ks++) {
            uint32_t kof = ks * 32;
            uint32_t bh[4][2], bl[4][2];
#pragma unroll
            for (int nt = 0; nt < 4; nt++) {
                uint32_t ab = sb + (b_r + nt * 8) * 80 + kof + b_kb;
                LDM2(bh[nt], ab + 2 * TILE_B);
                LDM2(bl[nt], ab + 3 * TILE_B);
            }
#pragma unroll
            for (int mt = 0; mt < 4; mt++) {
                uint32_t ah[4], al[4];
                uint32_t aa = sb + (a_r + mt * 16) * 80 + kof + a_kb;
                LDM4(ah, aa);
                LDM4(al, aa + TILE_B);
#pragma unroll
                for (int nt = 0; nt < 4; nt++) {
                    MMA16816(acc[mt][nt], ah, bh[nt]);
                    MMA16816(acc[mt][nt], ah, bl[nt]);
                    MMA16816(acc[mt][nt], al, bh[nt]);
                }
            }
        }
        __syncthreads();
    }

    // ---- epilogue ----
    float lg = 0.f;
    if (epi == EPI_MASK_SPLIT) {
        float gamma = 1.f / (1.f + expf(-decayp[0]));
        lg = logf(gamma);
    }
    C += (long)bz * bsc;
    if (Chi) { Chi += (long)bz * bsc; Clo += (long)bz * bsc; }

#pragma unroll
    for (int mt = 0; mt < 4; mt++) {
#pragma unroll
        for (int nt = 0; nt < 4; nt++) {
            long col = n0 + wn * 32 + nt * 8 + (lane & 3) * 2;
            long row0 = m0 + wm * 64 + mt * 16 + (lane >> 2);
#pragma unroll
            for (int e = 0; e < 4; e++) {
                long m = row0 + (e >> 1) * 8;
                long n = col + (e & 1);
                if (n >= N) continue;
                long idx = m * ldc + n;
                float v = acc[mt][nt][e];
                if (epi == EPI_STORE) C[idx] = v;
                else if (epi == EPI_STORE_SPLIT) {
                    C[idx] = v;
                    split2(v, Chi[idx], Clo[idx]);
                } else if (epi == EPI_MASK_SPLIT) {
                    float mv = (m > n) ? v * expf((float)(m - 1 - n) * lg) : 0.f;
                    split2(mv, Chi[idx], Clo[idx]);
                } else if (epi == EPI_ADD) C[idx] += v;
                else if (epi == EPI_ADD_SPLIT) {
                    float r = C[idx] + v;
                    C[idx] = r;
                    split2(r, Chi[idx], Clo[idx]);
                } else C[idx] = aux1[idx] + aux2[idx] + alpha * v;
            }
        }
    }
}

// ================= elementwise / SIMT kernels =================
__global__ void splitk_kernel(const float* __restrict__ src, __nv_bfloat16* __restrict__ h,
                              __nv_bfloat16* __restrict__ l, long n)
{
    long i = (long)blockIdx.x * 256 + threadIdx.x;
    if (i >= n) return;
    split2(src[i], h[i], l[i]);
}

__global__ void rmsnorm_kernel(const float* __restrict__ x, const float* __restrict__ w)
{
    int row = blockIdx.x;
    const float* xr = x + (long)row * DD;
    float s = 0.f;
    for (int i = threadIdx.x; i < DD; i += 256) { float v = xr[i]; s += v * v; }
    __shared__ float red[256];
    red[threadIdx.x] = s; __syncthreads();
    for (int o = 128; o > 0; o >>= 1) {
        if (threadIdx.x < o) red[threadIdx.x] += red[threadIdx.x + o];
        __syncthreads();
    }
    float r = rsqrtf(red[0] / (float)DD + 1e-6f);
    for (int i = threadIdx.x; i < DD; i += 256) {
        float v = xr[i] * r * w[i];
        long idx = (long)row * DD + i;
        split2(v, g_xnh[idx], g_xnl[idx]);
    }
}

__global__ void conv_silu_kernel(const float* __restrict__ cw, const float* __restrict__ cb)
{
    long idx = (long)blockIdx.x * 256 + threadIdx.x;
    if (idx >= (long)BL * DI) return;
    int c = (int)(idx % DI);
    long bl = idx / DI;
    int l = (int)(bl % LL);
    long b = bl / LL;
    float acc = cb[c];
#pragma unroll
    for (int k = 0; k < 4; k++) {
        int ls = l - 3 + k;
        if (ls >= 0) acc += cw[c * 4 + k] * g_proj[(b * LL + ls) * (long)PROJ + c];
    }
    g_val[idx] = acc / (1.f + expf(-acc));
}

__global__ void cum_kernel(const float* __restrict__ dt_bias, const float* __restrict__ A_log)
{
    int bid = blockIdx.x;
    int c = bid % NC; int h = (bid / NC) % HH; int b = bid / (NC * HH);
    int t = threadIdx.x;
    long row = (long)b * LL + c * CS + t;
    float x = g_proj[row * (long)PROJ + 2 * DI + 2 * HH * NN + h] + dt_bias[h];
    float sp = (x > 20.f) ? x : log1pf(expf(x));
    float ld = -expf(A_log[h]) * sp;
    __shared__ float s[256];
    s[t] = ld; __syncthreads();
    for (int o = 1; o < 256; o <<= 1) {
        float v = (t >= o) ? s[t - o] : 0.f;
        __syncthreads();
        s[t] += v;
        __syncthreads();
    }
    g_cum[(long)bid * CS + t] = s[t];
}

__global__ void __launch_bounds__(256) ssd_T_kernel()
{
    int bid = blockIdx.x;
    int c = bid % NC; int h = (bid / NC) % HH; int b = bid / (NC * HH);
    const float* cumc = g_cum + (long)bid * CS;
    __shared__ float vw[32][128];
    __shared__ float Bs[32][128];
    __shared__ float ew[CS];
    int t = threadIdx.x;
    float cl = cumc[CS - 1];
    for (int i = t; i < CS; i += 256) ew[i] = expf(cl - cumc[i]);
    __syncthreads();
    int tx = t & 15, ty = t >> 4;
    float acc[8][8];
#pragma unroll
    for (int r = 0; r < 8; r++)
#pragma unroll
        for (int cc = 0; cc < 8; cc++) acc[r][cc] = 0.f;
    long rowb = (long)b * LL + (long)c * CS;
    for (int k0 = 0; k0 < CS; k0 += 32) {
#pragma unroll
        for (int i = 0; i < 16; i++) {
            int e = t + i * 256; int kl = e >> 7; int j = e & 127;
            long row = rowb + k0 + kl;
            vw[kl][j] = g_val[row * (long)DI + h * HD + j] * ew[k0 + kl];
            Bs[kl][j] = g_proj[row * (long)PROJ + 2 * DI + h * NN + j];
        }
        __syncthreads();
#pragma unroll 8
        for (int kk = 0; kk < 32; kk++) {
            float a[8], bb[8];
#pragma unroll
            for (int r = 0; r < 8; r++) { a[r] = vw[kk][ty * 8 + r]; bb[r] = Bs[kk][tx * 8 + r]; }
#pragma unroll
            for (int r = 0; r < 8; r++)
#pragma unroll
                for (int cc = 0; cc < 8; cc++) acc[r][cc] += a[r] * bb[cc];
        }
        __syncthreads();
    }
    float* Tb = g_T + (long)bid * HD * NN;
#pragma unroll
    for (int r = 0; r < 8; r++)
#pragma unroll
        for (int cc = 0; cc < 8; cc++)
            Tb[(ty * 8 + r) * NN + tx * 8 + cc] = acc[r][cc];
}

__global__ void hscan_kernel()
{
    long i = (long)blockIdx.x * 256 + threadIdx.x;
    if (i >= (long)BB * HH * HD * NN) return;
    int dn = (int)(i % (HD * NN));
    long bh = i / (HD * NN);
    float hcur = 0.f;
    for (int c = 0; c < NC; c++) {
        long off = (bh * NC + c) * (long)(HD * NN) + dn;
        float Ac = expf(g_cum[(bh * NC + c) * CS + CS - 1]);
        g_hst[off] = hcur;
        hcur = Ac * hcur + g_T[off];
    }
}

__global__ void __launch_bounds__(256) ssd_Y_kernel(const float* __restrict__ Dskip)
{
    extern __shared__ float sm[];
    float* CsT = sm;
    float* buf = CsT + 128 * 65;
    float* Mt = buf + 8448;
    float* cumsh = Mt + 64 * 65;

    int bid = blockIdx.x;
    int lt = bid & 3;
    int bhc = bid >> 2;
    int c = bhc % NC; int bh = bhc / NC; int h = bh % HH; int b = bh / HH;
    int t = threadIdx.x, tx = t & 15, ty = t >> 4;
    const float* cumc = g_cum + (long)bhc * CS;
    for (int i = t; i < CS; i += 256) cumsh[i] = cumc[i];
    int l0 = lt * 64;
    long rowb = (long)b * LL + (long)c * CS;

#pragma unroll
    for (int i = 0; i < 32; i++) {
        int e = t + i * 256; int n = e & 127; int l = e >> 7;
        CsT[n * 65 + l] = g_proj[(rowb + l0 + l) * (long)PROJ + 2 * DI + HH * NN + h * NN + n];
    }
    __syncthreads();

    float acc[4][8];
#pragma unroll
    for (int r = 0; r < 4; r++)
#pragma unroll
        for (int cc = 0; cc < 8; cc++) acc[r][cc] = 0.f;

    for (int mt = 0; mt <= lt; mt++) {
        int m0 = mt * 64;
#pragma unroll
        for (int i = 0; i < 32; i++) {
            int e = t + i * 256; int n = e & 127; int m = e >> 7;
            buf[n * 65 + m] = g_proj[(rowb + m0 + m) * (long)PROJ + 2 * DI + h * NN + n];
        }
        __syncthreads();
        float am[4][4];
#pragma unroll
        for (int r = 0; r < 4; r++)
#pragma unroll
            for (int s = 0; s < 4; s++) am[r][s] = 0.f;
#pragma unroll 4
        for (int n = 0; n < 128; n++) {
            float a0[4], b0[4];
#pragma unroll
            for (int r = 0; r < 4; r++) { a0[r] = CsT[n * 65 + ty * 4 + r]; b0[r] = buf[n * 65 + tx * 4 + r]; }
#pragma unroll
            for (int r = 0; r < 4; r++)
#pragma unroll
                for (int s = 0; s < 4; s++) am[r][s] += a0[r] * b0[s];
        }
        __syncthreads();
#pragma unroll
        for (int r = 0; r < 4; r++)
#pragma unroll
            for (int s = 0; s < 4; s++) {
                int ll = ty * 4 + r, mm = tx * 4 + s;
                int gl = l0 + ll, gm = m0 + mm;
                Mt[ll * 65 + mm] = (gl >= gm) ? am[r][s] * expf(cumsh[gl] - cumsh[gm]) : 0.f;
            }
        __syncthreads();
#pragma unroll
        for (int i = 0; i < 32; i++) {
            int e = t + i * 256; int d = e & 127; int j = e >> 7;
            buf[j * 132 + d] = g_val[(rowb + m0 + j) * (long)DI + h * HD + d];
        }
        __syncthreads();
#pragma unroll 4
        for (int j = 0; j < 64; j++) {
            float a0[4], b0[8];
#pragma unroll
            for (int r = 0; r < 4; r++) a0[r] = Mt[(ty * 4 + r) * 65 + j];
#pragma unroll
            for (int cc = 0; cc < 8; cc++) b0[cc] = buf[j * 132 + tx * 8 + cc];
#pragma unroll
            for (int r = 0; r < 4; r++)
#pragma unroll
                for (int cc = 0; cc < 8; cc++) acc[r][cc] += a0[r] * b0[cc];
        }
        __syncthreads();
    }

    const float* hb = g_hst + (long)bhc * HD * NN;
    for (int nt = 0; nt < 8; nt++) {
        int n0 = nt * 16;
#pragma unroll
        for (int i = 0; i < 8; i++) {
            int e = t + i * 256; int j = e & 15; int d = e >> 4;
            buf[j * 132 + d] = hb[d * NN + n0 + j];
        }
        __syncthreads();
#pragma unroll
        for (int r = 0; r < 4; r++) {
            float el = expf(cumsh[l0 + ty * 4 + r]);
            float tmp[8];
#pragma unroll
            for (int cc = 0; cc < 8; cc++) tmp[cc] = 0.f;
#pragma unroll
            for (int j = 0; j < 16; j++) {
                float cv = CsT[(n0 + j) * 65 + ty * 4 + r];
#pragma unroll
                for (int cc = 0; cc < 8; cc++) tmp[cc] += cv * buf[j * 132 + tx * 8 + cc];
            }
#pragma unroll
            for (int cc = 0; cc < 8; cc++) acc[r][cc] += el * tmp[cc];
        }
        __syncthreads();
    }

#pragma unroll
    for (int r = 0; r < 4; r++) {
        int gl = l0 + ty * 4 + r;
        long grow = rowb + gl;
#pragma unroll
        for (int cc = 0; cc < 8; cc++) {
            int d = tx * 8 + cc;
            float vv = g_val[grow * (long)DI + h * HD + d];
            float y = acc[r][cc] + Dskip[h * HD + d] * vv;
            float g = g_proj[grow * (long)PROJ + DI + h * HD + d];
            float yo = y * g / (1.f + expf(-g));
            long idx = grow * (long)DI + h * HD + d;
            split2(yo, g_Ygh[idx], g_Ygl[idx]);
        }
    }
}

// fused memory-module prep: wk splits (+transposed), rkg splits, vgwT/vT splits
__global__ void memprep_kernel(const float* __restrict__ decayp)
{
    long i = (long)blockIdx.x * 256 + threadIdx.x;
    if (i >= (long)BL * DD) return;
    int d = (int)(i % DD);
    long bl = i / DD;
    int linb = (int)(bl % LL);
    long b = bl / LL;
    int tt = linb % MC, cz = linb / MC;
    float gamma = 1.f / (1.f + expf(-decayp[0]));
    float lg = logf(gamma);
    long dstT = (((long)b * NM + cz) * DD + d) * MC + tt;

    float wkv = (linb == 0) ? 0.f : g_out[i - DD];
    split2(wkv, g_wkh[i], g_wkl[i]);
    split2(wkv, g_wkTh[dstT], g_wkTl[dstT]);

    float rk = g_out[i] * expf((float)tt * lg);
    split2(rk, g_rkgh[i], g_rkgl[i]);

    float vv = g_v[i];
    split2(vv, g_vTh[dstT], g_vTl[dstT]);
    float vgw = vv * expf((float)(MC - 1 - tt) * lg);
    split2(vgw, g_vgwTh[dstT], g_vgwTl[dstT]);
}

__global__ void wscan_kernel(const float* __restrict__ decayp)
{
    long i = (long)blockIdx.x * 256 + threadIdx.x;
    if (i >= (long)BB * DD * DD) return;
    long de = i % ((long)DD * DD);
    long b = i / ((long)DD * DD);
    float gamma = 1.f / (1.f + expf(-decayp[0]));
    float gmc = expf(256.f * logf(gamma));
    float w = 0.f;
    for (int c = 0; c < NM; c++) {
        long off = (b * NM + c) * (long)(DD * DD) + de;
        split2(w, g_Wsth[off], g_Wstl[off]);
        w = gmc * w + g_U[off];
    }
}

// ================= host launcher =================
template <typename T>
static T* symaddr(const void* s)
{
    void* p = nullptr;
    cudaGetSymbolAddress(&p, s);
    return (T*)p;
}

extern "C" void kernel_launch(void* const* d_in, const int* in_sizes, int n_in,
                              void* d_out, int out_size)
{
    const float* x = (const float*)d_in[0];
    const float* norm_w = (const float*)d_in[1];
    const float* w_in = (const float*)d_in[2];
    const float* conv_w = (const float*)d_in[3];
    const float* conv_b = (const float*)d_in[4];
    const float* A_log = (const float*)d_in[5];
    const float* dt_bias = (const float*)d_in[6];
    const float* D_skip = (const float*)d_in[7];
    const float* w_out = (const float*)d_in[8];
    const float* w_write = (const float*)d_in[9];
    const float* w_read = (const float*)d_in[10];
    const float* decay = (const float*)d_in[11];
    float* out = (float*)d_out;

    typedef __nv_bfloat16 bf;
    float* p_proj  = symaddr<float>(g_proj);
    float* p_out   = symaddr<float>(g_out);
    float* p_v     = symaddr<float>(g_v);
    float* p_U     = symaddr<float>(g_U);
    float* p_reads = symaddr<float>(g_reads);
    bf *xnh = symaddr<bf>(g_xnh),   *xnl = symaddr<bf>(g_xnl);
    bf *winh = symaddr<bf>(g_winh), *winl = symaddr<bf>(g_winl);
    bf *Ygh = symaddr<bf>(g_Ygh),   *Ygl = symaddr<bf>(g_Ygl);
    bf *woh = symaddr<bf>(g_woh),   *wol = symaddr<bf>(g_wol);
    bf *outh = symaddr<bf>(g_outh), *outl = symaddr<bf>(g_outl);
    bf *wwh = symaddr<bf>(g_wwh),   *wwl = symaddr<bf>(g_wwl);
    bf *wrh = symaddr<bf>(g_wrh),   *wrl = symaddr<bf>(g_wrl);
    bf *wkh = symaddr<bf>(g_wkh),   *wkl = symaddr<bf>(g_wkl);
    bf *wkTh = symaddr<bf>(g_wkTh), *wkTl = symaddr<bf>(g_wkTl);
    bf *rkgh = symaddr<bf>(g_rkgh), *rkgl = symaddr<bf>(g_rkgl);
    bf *vgwTh = symaddr<bf>(g_vgwTh), *vgwTl = symaddr<bf>(g_vgwTl);
    bf *vTh = symaddr<bf>(g_vTh),   *vTl = symaddr<bf>(g_vTl);
    bf *Wsth = symaddr<bf>(g_Wsth), *Wstl = symaddr<bf>(g_Wstl);
    bf *Phh = symaddr<bf>(g_Ph),    *Pll = symaddr<bf>(g_Pl);
    bf *rdh = symaddr<bf>(g_rdh),   *rdl = symaddr<bf>(g_rdl);

    const int gsmem = 2 * STAGE_B;  // 81920
    cudaFuncSetAttribute(tgemm_kernel, cudaFuncAttributeMaxDynamicSharedMemorySize, gsmem);
    const int ysmem = (128 * 65 + 8448 + 64 * 65 + 256) * 4;
    cudaFuncSetAttribute(ssd_Y_kernel, cudaFuncAttributeMaxDynamicSharedMemorySize, ysmem);

    // weight splits
    splitk_kernel<<<(int)(((long)PROJ * DD + 255) / 256), 256>>>(w_in, winh, winl, (long)PROJ * DD);
    splitk_kernel<<<(int)(((long)DD * DI + 255) / 256), 256>>>(w_out, woh, wol, (long)DD * DI);
    splitk_kernel<<<(int)(((long)DD * DD + 255) / 256), 256>>>(w_write, wwh, wwl, (long)DD * DD);
    splitk_kernel<<<(int)(((long)DD * DD + 255) / 256), 256>>>(w_read, wrh, wrl, (long)DD * DD);

    rmsnorm_kernel<<<BL, 256>>>(x, norm_w);

    // proj = xn @ w_in^T  [8192 x 8208 x 1024]
    tgemm_kernel<<<dim3((PROJ + 127) / 128, BL / 128, 1), 256, gsmem>>>(
        xnh, xnl, winh, winl, p_proj, nullptr, nullptr,
        PROJ, DD, DD, DD, PROJ, 0, 0, 0, EPI_STORE, nullptr, nullptr, nullptr, 0.f);

    conv_silu_kernel<<<(int)(((long)BL * DI + 255) / 256), 256>>>(conv_w, conv_b);
    cum_kernel<<<BB * HH * NC, 256>>>(dt_bias, A_log);
    ssd_T_kernel<<<BB * HH * NC, 256>>>();
    hscan_kernel<<<(int)(((long)BB * HH * HD * NN + 255) / 256), 256>>>();
    ssd_Y_kernel<<<BB * HH * NC * 4, 256, ysmem>>>(D_skip);

    // out = Yg @ w_out^T  (store fp32 + splits)
    tgemm_kernel<<<dim3(DD / 128, BL / 128, 1), 256, gsmem>>>(
        Ygh, Ygl, woh, wol, p_out, outh, outl,
        DD, DI, DI, DI, DD, 0, 0, 0, EPI_STORE_SPLIT, nullptr, nullptr, nullptr, 0.f);

    // v = out @ w_write^T
    tgemm_kernel<<<dim3(DD / 128, BL / 128, 1), 256, gsmem>>>(
        outh, outl, wwh, wwl, p_v, nullptr, nullptr,
        DD, DD, DD, DD, DD, 0, 0, 0, EPI_STORE, nullptr, nullptr, nullptr, 0.f);

    // fused prep: wk (+T), rkg, vT, vgwT splits
    memprep_kernel<<<(int)(((long)BL * DD + 255) / 256), 256>>>(decay);

    // U[b,c,d,e] = sum_t vgwT[d,t]*wkT[e,t]
    tgemm_kernel<<<dim3(DD / 128, DD / 128, BB * NM), 256, gsmem>>>(
        vgwTh, vgwTl, wkTh, wkTl, p_U, nullptr, nullptr,
        DD, MC, MC, MC, DD,
        (long)DD * MC, (long)DD * MC, (long)DD * DD,
        EPI_STORE, nullptr, nullptr, nullptr, 0.f);

    wscan_kernel<<<(int)(((long)BB * DD * DD + 255) / 256), 256>>>(decay);

    // inter: reads = rkg @ Wst^T
    tgemm_kernel<<<dim3(DD / 128, MC / 128, BB * NM), 256, gsmem>>>(
        rkgh, rkgl, Wsth, Wstl, p_reads, nullptr, nullptr,
        DD, DD, DD, DD, DD,
        (long)MC * DD, (long)DD * DD, (long)MC * DD,
        EPI_STORE, nullptr, nullptr, nullptr, 0.f);

    // P = (out @ wk^T) * Mmem  -> split
    tgemm_kernel<<<dim3(MC / 128, MC / 128, BB * NM), 256, gsmem>>>(
        outh, outl, wkh, wkl, p_reads /*unused*/, Phh, Pll,
        MC, DD, DD, DD, MC,
        (long)MC * DD, (long)MC * DD, (long)MC * MC,
        EPI_MASK_SPLIT, nullptr, nullptr, decay, 0.f);

    // reads += P @ v  (B = vT), emit split of result
    tgemm_kernel<<<dim3(DD / 128, MC / 128, BB * NM), 256, gsmem>>>(
        Phh, Pll, vTh, vTl, p_reads, rdh, rdl,
        DD, MC, MC, MC, DD,
        (long)MC * MC, (long)DD * MC, (long)MC * DD,
        EPI_ADD_SPLIT, nullptr, nullptr, nullptr, 0.f);

    // final = x + out + 0.5 * reads @ w_read^T
    tgemm_kernel<<<dim3(DD / 128, BL / 128, 1), 256, gsmem>>>(
        rdh, rdl, wrh, wrl, out, nullptr, nullptr,
        DD, DD, DD, DD, DD, 0, 0, 0,
        EPI_FINAL, x, p_out, nullptr, ALPHA);
}

// round 11
// speedup vs baseline: 1.5587x; 1.1033x over previous
#include <cuda_runtime.h>
#include <cuda_bf16.h>
#include <math.h>
#include <stdint.h>

#define BB 2
#define LL 4096
#define DD 1024
#define DI 2048
#define HH 16
#define HD 128
#define NN 128
#define CS 256
#define NC 16
#define MC 256
#define NM 16
#define PROJ 8208
#define BL 8192
#define ALPHA 0.5f

// ================= fp32 scratch =================
static __device__ __align__(256) float g_proj[(size_t)BL * PROJ];
static __device__ __align__(256) float g_val[(size_t)BL * DI];
static __device__ __align__(256) float g_cum[(size_t)BB * HH * NC * CS];
static __device__ __align__(256) float g_T[(size_t)BB * HH * NC * HD * NN];
static __device__ __align__(256) float g_hst[(size_t)BB * HH * NC * HD * NN];
static __device__ __align__(256) float g_out[(size_t)BL * DD];
static __device__ __align__(256) float g_v[(size_t)BL * DD];
static __device__ __align__(256) float g_U[(size_t)BB * NM * DD * DD];
static __device__ __align__(256) float g_reads[(size_t)BL * DD];

// ================= bf16 split scratch =================
static __device__ __align__(256) __nv_bfloat16 g_xnh[(size_t)BL * DD],    g_xnl[(size_t)BL * DD];
static __device__ __align__(256) __nv_bfloat16 g_winh[(size_t)PROJ * DD], g_winl[(size_t)PROJ * DD];
static __device__ __align__(256) __nv_bfloat16 g_Ygh[(size_t)BL * DI],    g_Ygl[(size_t)BL * DI];
static __device__ __align__(256) __nv_bfloat16 g_woh[(size_t)DD * DI],    g_wol[(size_t)DD * DI];
static __device__ __align__(256) __nv_bfloat16 g_outh[(size_t)BL * DD],   g_outl[(size_t)BL * DD];
static __device__ __align__(256) __nv_bfloat16 g_wwh[(size_t)DD * DD],    g_wwl[(size_t)DD * DD];
static __device__ __align__(256) __nv_bfloat16 g_wrh[(size_t)DD * DD],    g_wrl[(size_t)DD * DD];
static __device__ __align__(256) __nv_bfloat16 g_wkh[(size_t)BL * DD],    g_wkl[(size_t)BL * DD];
static __device__ __align__(256) __nv_bfloat16 g_wkTh[(size_t)BL * DD],   g_wkTl[(size_t)BL * DD];
static __device__ __align__(256) __nv_bfloat16 g_rkgh[(size_t)BL * DD],   g_rkgl[(size_t)BL * DD];
static __device__ __align__(256) __nv_bfloat16 g_vgwTh[(size_t)BL * DD],  g_vgwTl[(size_t)BL * DD];
static __device__ __align__(256) __nv_bfloat16 g_vTh[(size_t)BL * DD],    g_vTl[(size_t)BL * DD];
static __device__ __align__(256) __nv_bfloat16 g_Wsth[(size_t)BB * NM * DD * DD], g_Wstl[(size_t)BB * NM * DD * DD];
static __device__ __align__(256) __nv_bfloat16 g_Ph[(size_t)BB * NM * MC * MC],   g_Pl[(size_t)BB * NM * MC * MC];
static __device__ __align__(256) __nv_bfloat16 g_rdh[(size_t)BL * DD],    g_rdl[(size_t)BL * DD];

enum { EPI_STORE = 0, EPI_MASK_SPLIT = 1, EPI_ADD = 2, EPI_FINAL = 3, EPI_STORE_SPLIT = 4, EPI_ADD_SPLIT = 5 };

// ================= ptx helpers (all plain sm_80+ features) =================
__device__ __forceinline__ uint32_t smem_u32(const void* p) {
    uint32_t a;
    asm("{ .reg .u64 tmp; cvta.to.shared.u64 tmp, %1; cvt.u32.u64 %0, tmp; }" : "=r"(a) : "l"(p));
    return a;
}
__device__ __forceinline__ void cp16(uint32_t dst, const void* src, int ok) {
    int sz = ok ? 16 : 0;
    asm volatile("cp.async.cg.shared.global [%0], [%1], 16, %2;" :: "r"(dst), "l"(src), "r"(sz) : "memory");
}
#define CP_COMMIT() asm volatile("cp.async.commit_group;" ::: "memory")
#define CP_WAIT1()  asm volatile("cp.async.wait_group 1;" ::: "memory")
#define CP_WAIT0()  asm volatile("cp.async.wait_group 0;" ::: "memory")

#define LDM4(r, a) \
    asm volatile("ldmatrix.sync.aligned.m8n8.x4.shared.b16 {%0,%1,%2,%3}, [%4];" \
        : "=r"((r)[0]), "=r"((r)[1]), "=r"((r)[2]), "=r"((r)[3]) : "r"(a))
#define LDM2(r, a) \
    asm volatile("ldmatrix.sync.aligned.m8n8.x2.shared.b16 {%0,%1}, [%2];" \
        : "=r"((r)[0]), "=r"((r)[1]) : "r"(a))
#define MMA16816(c, a, b) \
    asm volatile("mma.sync.aligned.m16n8k16.row.col.f32.bf16.bf16.f32 " \
        "{%0,%1,%2,%3}, {%4,%5,%6,%7}, {%8,%9}, {%0,%1,%2,%3};" \
        : "+f"((c)[0]), "+f"((c)[1]), "+f"((c)[2]), "+f"((c)[3]) \
        : "r"((a)[0]), "r"((a)[1]), "r"((a)[2]), "r"((a)[3]), "r"((b)[0]), "r"((b)[1]))

__device__ __forceinline__ void split2(float v, __nv_bfloat16& h, __nv_bfloat16& l) {
    h = __float2bfloat16(v);
    l = __float2bfloat16(v - __bfloat162float(h));
}

// ================= mma.sync split-bf16 GEMM =================
// C[m,n] = sum_k A[m,k]*B[n,k], via Ahi*Bhi + Ahi*Blo + Alo*Bhi
// block tile 128x128, BK=32, 256 threads (8 warps, 2x4), warp tile 64x32.
// smem per stage: 4 tiles (Ah,Al,Bh,Bl), each 128 rows x 80B. 2-stage.
// Supertile rasterization (GROUP_M=16) for L2 reuse across concurrent CTAs.
#define TILE_B 10240
#define STAGE_B 40960
__global__ void __launch_bounds__(256) tgemm_kernel(
    const __nv_bfloat16* __restrict__ Ahi, const __nv_bfloat16* __restrict__ Alo,
    const __nv_bfloat16* __restrict__ Bhi, const __nv_bfloat16* __restrict__ Blo,
    float* __restrict__ C, __nv_bfloat16* __restrict__ Chi, __nv_bfloat16* __restrict__ Clo,
    int N, int K, long lda, long ldb, long ldc,
    long bsa, long bsb, long bsc,
    int epi, const float* __restrict__ aux1, const float* __restrict__ aux2,
    const float* __restrict__ decayp, float alpha)
{
    extern __shared__ char smem[];
    uint32_t sbase = smem_u32(smem);
    int t = threadIdx.x, lane = t & 31, wid = t >> 5;
    int wm = wid >> 2, wn = wid & 3;

    int bz = blockIdx.z;
    Ahi += (long)bz * bsa; Alo += (long)bz * bsa;
    Bhi += (long)bz * bsb; Blo += (long)bz * bsb;

    // ---- supertile swizzle: consecutive pids cover a GM x * tile block ----
    int gx = gridDim.x, gy = gridDim.y;
    int pid = blockIdx.y * gx + blockIdx.x;
    const int GM = 16;
    int npg = GM * gx;
    int gid = pid / npg;
    int fm = gid * GM;
    int gsz = min(gy - fm, GM);
    int bm = fm + (pid % gsz);
    int bn = (pid % npg) / gsz;
    long m0 = (long)bm * 128, n0 = (long)bn * 128;

    float acc[4][4][4];
#pragma unroll
    for (int mt = 0; mt < 4; mt++)
#pragma unroll
        for (int nt = 0; nt < 4; nt++)
#pragma unroll
            for (int e = 0; e < 4; e++) acc[mt][nt][e] = 0.f;

    int nk = K >> 5;  // K-chunks of 32

    auto load_stage = [&](int s, int ck) {
        long k0 = (long)ck * 32;
        uint32_t sb = sbase + s * STAGE_B;
#pragma unroll
        for (int i = 0; i < 8; i++) {
            int ch = t + i * 256;
            int tile = ch >> 9; int idx = ch & 511; int row = idx >> 2; int part = idx & 3;
            uint32_t dst = sb + tile * TILE_B + row * 80 + part * 16;
            const __nv_bfloat16* srcp;
            int ok = 1;
            if (tile == 0)      srcp = Ahi + (m0 + row) * lda + k0 + part * 8;
            else if (tile == 1) srcp = Alo + (m0 + row) * lda + k0 + part * 8;
            else {
                ok = (n0 + row) < N;
                long r = ok ? (n0 + row) : 0;
                srcp = ((tile == 2) ? Bhi : Blo) + r * ldb + k0 + part * 8;
            }
            cp16(dst, srcp, ok);
        }
        CP_COMMIT();
    };

    load_stage(0, 0);

    for (int ck = 0; ck < nk; ck++) {
        int s = ck & 1;
        if (ck + 1 < nk) { load_stage(s ^ 1, ck + 1); CP_WAIT1(); }
        else CP_WAIT0();
        __syncthreads();

        uint32_t sb = sbase + s * STAGE_B;
        uint32_t a_r = (uint32_t)(wm * 64 + (lane & 15));
        uint32_t a_kb = (uint32_t)((lane >> 4) * 16);
        uint32_t b_r = (uint32_t)(wn * 32 + (lane & 7));
        uint32_t b_kb = (uint32_t)(((lane >> 3) & 1) * 16);
#pragma unroll
        for (int ks = 0; ks < 2; ks++) {
            uint32_t kof = ks * 32;
            uint32_t bh[4][2], bl[4][2];
#pragma unroll
            for (int nt = 0; nt < 4; nt++) {
                uint32_t ab = sb + (b_r + nt * 8) * 80 + kof + b_kb;
                LDM2(bh[nt], ab + 2 * TILE_B);
                LDM2(bl[nt], ab + 3 * TILE_B);
            }
#pragma unroll
            for (int mt = 0; mt < 4; mt++) {
                uint32_t ah[4], al[4];
                uint32_t aa = sb + (a_r + mt * 16) * 80 + kof + a_kb;
                LDM4(ah, aa);
                LDM4(al, aa + TILE_B);
#pragma unroll
                for (int nt = 0; nt < 4; nt++) {
                    MMA16816(acc[mt][nt], ah, bh[nt]);
                    MMA16816(acc[mt][nt], ah, bl[nt]);
                    MMA16816(acc[mt][nt], al, bh[nt]);
                }
            }
        }
        __syncthreads();
    }

    // ---- epilogue ----
    float lg = 0.f;
    if (epi == EPI_MASK_SPLIT) {
        float gamma = 1.f / (1.f + expf(-decayp[0]));
        lg = logf(gamma);
    }
    C += (long)bz * bsc;
    if (Chi) { Chi += (long)bz * bsc; Clo += (long)bz * bsc; }

#pragma unroll
    for (int mt = 0; mt < 4; mt++) {
#pragma unroll
        for (int nt = 0; nt < 4; nt++) {
            long col = n0 + wn * 32 + nt * 8 + (lane & 3) * 2;
            long row0 = m0 + wm * 64 + mt * 16 + (lane >> 2);
#pragma unroll
            for (int e = 0; e < 4; e++) {
                long m = row0 + (e >> 1) * 8;
                long n = col + (e & 1);
                if (n >= N) continue;
                long idx = m * ldc + n;
                float v = acc[mt][nt][e];
                if (epi == EPI_STORE) C[idx] = v;
                else if (epi == EPI_STORE_SPLIT) {
                    C[idx] = v;
                    split2(v, Chi[idx], Clo[idx]);
                } else if (epi == EPI_MASK_SPLIT) {
                    float mv = (m > n) ? v * expf((float)(m - 1 - n) * lg) : 0.f;
                    split2(mv, Chi[idx], Clo[idx]);
                } else if (epi == EPI_ADD) C[idx] += v;
                else if (epi == EPI_ADD_SPLIT) {
                    float r = C[idx] + v;
                    C[idx] = r;
                    split2(r, Chi[idx], Clo[idx]);
                } else C[idx] = aux1[idx] + aux2[idx] + alpha * v;
            }
        }
    }
}

// ================= elementwise / SIMT kernels =================
__global__ void splitk_kernel(const float* __restrict__ src, __nv_bfloat16* __restrict__ h,
                              __nv_bfloat16* __restrict__ l, long n)
{
    long i = (long)blockIdx.x * 256 + threadIdx.x;
    if (i >= n) return;
    split2(src[i], h[i], l[i]);
}

__global__ void rmsnorm_kernel(const float* __restrict__ x, const float* __restrict__ w)
{
    int row = blockIdx.x;
    const float* xr = x + (long)row * DD;
    float s = 0.f;
    for (int i = threadIdx.x; i < DD; i += 256) { float v = xr[i]; s += v * v; }
    __shared__ float red[256];
    red[threadIdx.x] = s; __syncthreads();
    for (int o = 128; o > 0; o >>= 1) {
        if (threadIdx.x < o) red[threadIdx.x] += red[threadIdx.x + o];
        __syncthreads();
    }
    float r = rsqrtf(red[0] / (float)DD + 1e-6f);
    for (int i = threadIdx.x; i < DD; i += 256) {
        float v = xr[i] * r * w[i];
        long idx = (long)row * DD + i;
        split2(v, g_xnh[idx], g_xnl[idx]);
    }
}

__global__ void conv_silu_kernel(const float* __restrict__ cw, const float* __restrict__ cb)
{
    long idx = (long)blockIdx.x * 256 + threadIdx.x;
    if (idx >= (long)BL * DI) return;
    int c = (int)(idx % DI);
    long bl = idx / DI;
    int l = (int)(bl % LL);
    long b = bl / LL;
    float acc = cb[c];
#pragma unroll
    for (int k = 0; k < 4; k++) {
        int ls = l - 3 + k;
        if (ls >= 0) acc += cw[c * 4 + k] * g_proj[(b * LL + ls) * (long)PROJ + c];
    }
    g_val[idx] = acc / (1.f + expf(-acc));
}

__global__ void cum_kernel(const float* __restrict__ dt_bias, const float* __restrict__ A_log)
{
    int bid = blockIdx.x;
    int c = bid % NC; int h = (bid / NC) % HH; int b = bid / (NC * HH);
    int t = threadIdx.x;
    long row = (long)b * LL + c * CS + t;
    float x = g_proj[row * (long)PROJ + 2 * DI + 2 * HH * NN + h] + dt_bias[h];
    float sp = (x > 20.f) ? x : log1pf(expf(x));
    float ld = -expf(A_log[h]) * sp;
    __shared__ float s[256];
    s[t] = ld; __syncthreads();
    for (int o = 1; o < 256; o <<= 1) {
        float v = (t >= o) ? s[t - o] : 0.f;
        __syncthreads();
        s[t] += v;
        __syncthreads();
    }
    g_cum[(long)bid * CS + t] = s[t];
}

__global__ void __launch_bounds__(256) ssd_T_kernel()
{
    int bid = blockIdx.x;
    int c = bid % NC; int h = (bid / NC) % HH; int b = bid / (NC * HH);
    const float* cumc = g_cum + (long)bid * CS;
    __shared__ float vw[32][128];
    __shared__ float Bs[32][128];
    __shared__ float ew[CS];
    int t = threadIdx.x;
    float cl = cumc[CS - 1];
    for (int i = t; i < CS; i += 256) ew[i] = expf(cl - cumc[i]);
    __syncthreads();
    int tx = t & 15, ty = t >> 4;
    float acc[8][8];
#pragma unroll
    for (int r = 0; r < 8; r++)
#pragma unroll
        for (int cc = 0; cc < 8; cc++) acc[r][cc] = 0.f;
    long rowb = (long)b * LL + (long)c * CS;
    for (int k0 = 0; k0 < CS; k0 += 32) {
#pragma unroll
        for (int i = 0; i < 16; i++) {
            int e = t + i * 256; int kl = e >> 7; int j = e & 127;
            long row = rowb + k0 + kl;
            vw[kl][j] = g_val[row * (long)DI + h * HD + j] * ew[k0 + kl];
            Bs[kl][j] = g_proj[row * (long)PROJ + 2 * DI + h * NN + j];
        }
        __syncthreads();
#pragma unroll 8
        for (int kk = 0; kk < 32; kk++) {
            float a[8], bb[8];
#pragma unroll
            for (int r = 0; r < 8; r++) { a[r] = vw[kk][ty * 8 + r]; bb[r] = Bs[kk][tx * 8 + r]; }
#pragma unroll
            for (int r = 0; r < 8; r++)
#pragma unroll
                for (int cc = 0; cc < 8; cc++) acc[r][cc] += a[r] * bb[cc];
        }
        __syncthreads();
    }
    float* Tb = g_T + (long)bid * HD * NN;
#pragma unroll
    for (int r = 0; r < 8; r++)
#pragma unroll
        for (int cc = 0; cc < 8; cc++)
            Tb[(ty * 8 + r) * NN + tx * 8 + cc] = acc[r][cc];
}

__global__ void hscan_kernel()
{
    long i = (long)blockIdx.x * 256 + threadIdx.x;
    if (i >= (long)BB * HH * HD * NN) return;
    int dn = (int)(i % (HD * NN));
    long bh = i / (HD * NN);
    float hcur = 0.f;
    for (int c = 0; c < NC; c++) {
        long off = (bh * NC + c) * (long)(HD * NN) + dn;
        float Ac = expf(g_cum[(bh * NC + c) * CS + CS - 1]);
        g_hst[off] = hcur;
        hcur = Ac * hcur + g_T[off];
    }
}

__global__ void __launch_bounds__(256) ssd_Y_kernel(const float* __restrict__ Dskip)
{
    extern __shared__ float sm[];
    float* CsT = sm;
    float* buf = CsT + 128 * 65;
    float* Mt = buf + 8448;
    float* cumsh = Mt + 64 * 65;

    int bid = blockIdx.x;
    int lt = bid & 3;
    int bhc = bid >> 2;
    int c = bhc % NC; int bh = bhc / NC; int h = bh % HH; int b = bh / HH;
    int t = threadIdx.x, tx = t & 15, ty = t >> 4;
    const float* cumc = g_cum + (long)bhc * CS;
    for (int i = t; i < CS; i += 256) cumsh[i] = cumc[i];
    int l0 = lt * 64;
    long rowb = (long)b * LL + (long)c * CS;

#pragma unroll
    for (int i = 0; i < 32; i++) {
        int e = t + i * 256; int n = e & 127; int l = e >> 7;
        CsT[n * 65 + l] = g_proj[(rowb + l0 + l) * (long)PROJ + 2 * DI + HH * NN + h * NN + n];
    }
    __syncthreads();

    float acc[4][8];
#pragma unroll
    for (int r = 0; r < 4; r++)
#pragma unroll
        for (int cc = 0; cc < 8; cc++) acc[r][cc] = 0.f;

    for (int mt = 0; mt <= lt; mt++) {
        int m0 = mt * 64;
#pragma unroll
        for (int i = 0; i < 32; i++) {
            int e = t + i * 256; int n = e & 127; int m = e >> 7;
            buf[n * 65 + m] = g_proj[(rowb + m0 + m) * (long)PROJ + 2 * DI + h * NN + n];
        }
        __syncthreads();
        float am[4][4];
#pragma unroll
        for (int r = 0; r < 4; r++)
#pragma unroll
            for (int s = 0; s < 4; s++) am[r][s] = 0.f;
#pragma unroll 4
        for (int n = 0; n < 128; n++) {
            float a0[4], b0[4];
#pragma unroll
            for (int r = 0; r < 4; r++) { a0[r] = CsT[n * 65 + ty * 4 + r]; b0[r] = buf[n * 65 + tx * 4 + r]; }
#pragma unroll
            for (int r = 0; r < 4; r++)
#pragma unroll
                for (int s = 0; s < 4; s++) am[r][s] += a0[r] * b0[s];
        }
        __syncthreads();
#pragma unroll
        for (int r = 0; r < 4; r++)
#pragma unroll
            for (int s = 0; s < 4; s++) {
                int ll = ty * 4 + r, mm = tx * 4 + s;
                int gl = l0 + ll, gm = m0 + mm;
                Mt[ll * 65 + mm] = (gl >= gm) ? am[r][s] * expf(cumsh[gl] - cumsh[gm]) : 0.f;
            }
        __syncthreads();
#pragma unroll
        for (int i = 0; i < 32; i++) {
            int e = t + i * 256; int d = e & 127; int j = e >> 7;
            buf[j * 132 + d] = g_val[(rowb + m0 + j) * (long)DI + h * HD + d];
        }
        __syncthreads();
#pragma unroll 4
        for (int j = 0; j < 64; j++) {
            float a0[4], b0[8];
#pragma unroll
            for (int r = 0; r < 4; r++) a0[r] = Mt[(ty * 4 + r) * 65 + j];
#pragma unroll
            for (int cc = 0; cc < 8; cc++) b0[cc] = buf[j * 132 + tx * 8 + cc];
#pragma unroll
            for (int r = 0; r < 4; r++)
#pragma unroll
                for (int cc = 0; cc < 8; cc++) acc[r][cc] += a0[r] * b0[cc];
        }
        __syncthreads();
    }

    const float* hb = g_hst + (long)bhc * HD * NN;
    for (int nt = 0; nt < 8; nt++) {
        int n0 = nt * 16;
#pragma unroll
        for (int i = 0; i < 8; i++) {
            int e = t + i * 256; int j = e & 15; int d = e >> 4;
            buf[j * 132 + d] = hb[d * NN + n0 + j];
        }
        __syncthreads();
#pragma unroll
        for (int r = 0; r < 4; r++) {
            float el = expf(cumsh[l0 + ty * 4 + r]);
            float tmp[8];
#pragma unroll
            for (int cc = 0; cc < 8; cc++) tmp[cc] = 0.f;
#pragma unroll
            for (int j = 0; j < 16; j++) {
                float cv = CsT[(n0 + j) * 65 + ty * 4 + r];
#pragma unroll
                for (int cc = 0; cc < 8; cc++) tmp[cc] += cv * buf[j * 132 + tx * 8 + cc];
            }
#pragma unroll
            for (int cc = 0; cc < 8; cc++) acc[r][cc] += el * tmp[cc];
        }
        __syncthreads();
    }

#pragma unroll
    for (int r = 0; r < 4; r++) {
        int gl = l0 + ty * 4 + r;
        long grow = rowb + gl;
#pragma unroll
        for (int cc = 0; cc < 8; cc++) {
            int d = tx * 8 + cc;
            float vv = g_val[grow * (long)DI + h * HD + d];
            float y = acc[r][cc] + Dskip[h * HD + d] * vv;
            float g = g_proj[grow * (long)PROJ + DI + h * HD + d];
            float yo = y * g / (1.f + expf(-g));
            long idx = grow * (long)DI + h * HD + d;
            split2(yo, g_Ygh[idx], g_Ygl[idx]);
        }
    }
}

// fused memory-module prep: wk splits (+transposed), rkg splits, vgwT/vT splits
__global__ void memprep_kernel(const float* __restrict__ decayp)
{
    long i = (long)blockIdx.x * 256 + threadIdx.x;
    if (i >= (long)BL * DD) return;
    int d = (int)(i % DD);
    long bl = i / DD;
    int linb = (int)(bl % LL);
    long b = bl / LL;
    int tt = linb % MC, cz = linb / MC;
    float gamma = 1.f / (1.f + expf(-decayp[0]));
    float lg = logf(gamma);
    long dstT = (((long)b * NM + cz) * DD + d) * MC + tt;

    float wkv = (linb == 0) ? 0.f : g_out[i - DD];
    split2(wkv, g_wkh[i], g_wkl[i]);
    split2(wkv, g_wkTh[dstT], g_wkTl[dstT]);

    float rk = g_out[i] * expf((float)tt * lg);
    split2(rk, g_rkgh[i], g_rkgl[i]);

    float vv = g_v[i];
    split2(vv, g_vTh[dstT], g_vTl[dstT]);
    float vgw = vv * expf((float)(MC - 1 - tt) * lg);
    split2(vgw, g_vgwTh[dstT], g_vgwTl[dstT]);
}

__global__ void wscan_kernel(const float* __restrict__ decayp)
{
    long i = (long)blockIdx.x * 256 + threadIdx.x;
    if (i >= (long)BB * DD * DD) return;
    long de = i % ((long)DD * DD);
    long b = i / ((long)DD * DD);
    float gamma = 1.f / (1.f + expf(-decayp[0]));
    float gmc = expf(256.f * logf(gamma));
    float w = 0.f;
    for (int c = 0; c < NM; c++) {
        long off = (b * NM + c) * (long)(DD * DD) + de;
        split2(w, g_Wsth[off], g_Wstl[off]);
        w = gmc * w + g_U[off];
    }
}

// ================= host launcher =================
template <typename T>
static T* symaddr(const void* s)
{
    void* p = nullptr;
    cudaGetSymbolAddress(&p, s);
    return (T*)p;
}

extern "C" void kernel_launch(void* const* d_in, const int* in_sizes, int n_in,
                              void* d_out, int out_size)
{
    const float* x = (const float*)d_in[0];
    const float* norm_w = (const float*)d_in[1];
    const float* w_in = (const float*)d_in[2];
    const float* conv_w = (const float*)d_in[3];
    const float* conv_b = (const float*)d_in[4];
    const float* A_log = (const float*)d_in[5];
    const float* dt_bias = (const float*)d_in[6];
    const float* D_skip = (const float*)d_in[7];
    const float* w_out = (const float*)d_in[8];
    const float* w_write = (const float*)d_in[9];
    const float* w_read = (const float*)d_in[10];
    const float* decay = (const float*)d_in[11];
    float* out = (float*)d_out;

    typedef __nv_bfloat16 bf;
    float* p_proj  = symaddr<float>(g_proj);
    float* p_out   = symaddr<float>(g_out);
    float* p_v     = symaddr<float>(g_v);
    float* p_U     = symaddr<float>(g_U);
    float* p_reads = symaddr<float>(g_reads);
    bf *xnh = symaddr<bf>(g_xnh),   *xnl = symaddr<bf>(g_xnl);
    bf *winh = symaddr<bf>(g_winh), *winl = symaddr<bf>(g_winl);
    bf *Ygh = symaddr<bf>(g_Ygh),   *Ygl = symaddr<bf>(g_Ygl);
    bf *woh = symaddr<bf>(g_woh),   *wol = symaddr<bf>(g_wol);
    bf *outh = symaddr<bf>(g_outh), *outl = symaddr<bf>(g_outl);
    bf *wwh = symaddr<bf>(g_wwh),   *wwl = symaddr<bf>(g_wwl);
    bf *wrh = symaddr<bf>(g_wrh),   *wrl = symaddr<bf>(g_wrl);
    bf *wkh = symaddr<bf>(g_wkh),   *wkl = symaddr<bf>(g_wkl);
    bf *wkTh = symaddr<bf>(g_wkTh), *wkTl = symaddr<bf>(g_wkTl);
    bf *rkgh = symaddr<bf>(g_rkgh), *rkgl = symaddr<bf>(g_rkgl);
    bf *vgwTh = symaddr<bf>(g_vgwTh), *vgwTl = symaddr<bf>(g_vgwTl);
    bf *vTh = symaddr<bf>(g_vTh),   *vTl = symaddr<bf>(g_vTl);
    bf *Wsth = symaddr<bf>(g_Wsth), *Wstl = symaddr<bf>(g_Wstl);
    bf *Phh = symaddr<bf>(g_Ph),    *Pll = symaddr<bf>(g_Pl);
    bf *rdh = symaddr<bf>(g_rdh),   *rdl = symaddr<bf>(g_rdl);

    const int gsmem = 2 * STAGE_B;  // 81920
    cudaFuncSetAttribute(tgemm_kernel, cudaFuncAttributeMaxDynamicSharedMemorySize, gsmem);
    const int ysmem = (128 * 65 + 8448 + 64 * 65 + 256) * 4;
    cudaFuncSetAttribute(ssd_Y_kernel, cudaFuncAttributeMaxDynamicSharedMemorySize, ysmem);

    // rmsnorm first (keeps proj as the 6th launch for ncu -s 5 -c 1)
    rmsnorm_kernel<<<BL, 256>>>(x, norm_w);

    // weight splits
    splitk_kernel<<<(int)(((long)PROJ * DD + 255) / 256), 256>>>(w_in, winh, winl, (long)PROJ * DD);
    splitk_kernel<<<(int)(((long)DD * DI + 255) / 256), 256>>>(w_out, woh, wol, (long)DD * DI);
    splitk_kernel<<<(int)(((long)DD * DD + 255) / 256), 256>>>(w_write, wwh, wwl, (long)DD * DD);
    splitk_kernel<<<(int)(((long)DD * DD + 255) / 256), 256>>>(w_read, wrh, wrl, (long)DD * DD);

    // proj = xn @ w_in^T  [8192 x 8208 x 1024]
    tgemm_kernel<<<dim3((PROJ + 127) / 128, BL / 128, 1), 256, gsmem>>>(
        xnh, xnl, winh, winl, p_proj, nullptr, nullptr,
        PROJ, DD, DD, DD, PROJ, 0, 0, 0, EPI_STORE, nullptr, nullptr, nullptr, 0.f);

    conv_silu_kernel<<<(int)(((long)BL * DI + 255) / 256), 256>>>(conv_w, conv_b);
    cum_kernel<<<BB * HH * NC, 256>>>(dt_bias, A_log);
    ssd_T_kernel<<<BB * HH * NC, 256>>>();
    hscan_kernel<<<(int)(((long)BB * HH * HD * NN + 255) / 256), 256>>>();
    ssd_Y_kernel<<<BB * HH * NC * 4, 256, ysmem>>>(D_skip);

    // out = Yg @ w_out^T  (store fp32 + splits)
    tgemm_kernel<<<dim3(DD / 128, BL / 128, 1), 256, gsmem>>>(
        Ygh, Ygl, woh, wol, p_out, outh, outl,
        DD, DI, DI, DI, DD, 0, 0, 0, EPI_STORE_SPLIT, nullptr, nullptr, nullptr, 0.f);

    // v = out @ w_write^T
    tgemm_kernel<<<dim3(DD / 128, BL / 128, 1), 256, gsmem>>>(
        outh, outl, wwh, wwl, p_v, nullptr, nullptr,
        DD, DD, DD, DD, DD, 0, 0, 0, EPI_STORE, nullptr, nullptr, nullptr, 0.f);

    // fused prep: wk (+T), rkg, vT, vgwT splits
    memprep_kernel<<<(int)(((long)BL * DD + 255) / 256), 256>>>(decay);

    // U[b,c,d,e] = sum_t vgwT[d,t]*wkT[e,t]
    tgemm_kernel<<<dim3(DD / 128, DD / 128, BB * NM), 256, gsmem>>>(
        vgwTh, vgwTl, wkTh, wkTl, p_U, nullptr, nullptr,
        DD, MC, MC, MC, DD,
        (long)DD * MC, (long)DD * MC, (long)DD * DD,
        EPI_STORE, nullptr, nullptr, nullptr, 0.f);

    wscan_kernel<<<(int)(((long)BB * DD * DD + 255) / 256), 256>>>(decay);

    // inter: reads = rkg @ Wst^T
    tgemm_kernel<<<dim3(DD / 128, MC / 128, BB * NM), 256, gsmem>>>(
        rkgh, rkgl, Wsth, Wstl, p_reads, nullptr, nullptr,
        DD, DD, DD, DD, DD,
        (long)MC * DD, (long)DD * DD, (long)MC * DD,
        EPI_STORE, nullptr, nullptr, nullptr, 0.f);

    // P = (out @ wk^T) * Mmem  -> split
    tgemm_kernel<<<dim3(MC / 128, MC / 128, BB * NM), 256, gsmem>>>(
        outh, outl, wkh, wkl, p_reads /*unused*/, Phh, Pll,
        MC, DD, DD, DD, MC,
        (long)MC * DD, (long)MC * DD, (long)MC * MC,
        EPI_MASK_SPLIT, nullptr, nullptr, decay, 0.f);

    // reads += P @ v  (B = vT), emit split of result
    tgemm_kernel<<<dim3(DD / 128, MC / 128, BB * NM), 256, gsmem>>>(
        Phh, Pll, vTh, vTl, p_reads, rdh, rdl,
        DD, MC, MC, MC, DD,
        (long)MC * MC, (long)DD * MC, (long)MC * DD,
        EPI_ADD_SPLIT, nullptr, nullptr, nullptr, 0.f);

    // final = x + out + 0.5 * reads @ w_read^T
    tgemm_kernel<<<dim3(DD / 128, BL / 128, 1), 256, gsmem>>>(
        rdh, rdl, wrh, wrl, out, nullptr, nullptr,
        DD, DD, DD, DD, DD, 0, 0, 0,
        EPI_FINAL, x, p_out, nullptr, ALPHA);
}

// round 14
// speedup vs baseline: 1.6462x; 1.0561x over previous
#include <cuda_runtime.h>
#include <cuda_bf16.h>
#include <math.h>
#include <stdint.h>

#define BB 2
#define LL 4096
#define DD 1024
#define DI 2048
#define HH 16
#define HD 128
#define NN 128
#define CS 256
#define NC 16
#define MC 256
#define NM 16
#define PROJ 8208
#define BL 8192
#define ALPHA 0.5f

// ================= fp32 scratch =================
static __device__ __align__(256) float g_proj[(size_t)BL * PROJ];
static __device__ __align__(256) float g_val[(size_t)BL * DI];
static __device__ __align__(256) float g_cum[(size_t)BB * HH * NC * CS];
static __device__ __align__(256) float g_T[(size_t)BB * HH * NC * HD * NN];
static __device__ __align__(256) float g_out[(size_t)BL * DD];
static __device__ __align__(256) float g_v[(size_t)BL * DD];
static __device__ __align__(256) float g_U[(size_t)BB * NM * DD * DD];
static __device__ __align__(256) float g_reads[(size_t)BL * DD];

// ================= bf16 split scratch =================
static __device__ __align__(256) __nv_bfloat16 g_xnh[(size_t)BL * DD],    g_xnl[(size_t)BL * DD];
static __device__ __align__(256) __nv_bfloat16 g_winh[(size_t)PROJ * DD], g_winl[(size_t)PROJ * DD];
static __device__ __align__(256) __nv_bfloat16 g_Ygh[(size_t)BL * DI],    g_Ygl[(size_t)BL * DI];
static __device__ __align__(256) __nv_bfloat16 g_woh[(size_t)DD * DI],    g_wol[(size_t)DD * DI];
static __device__ __align__(256) __nv_bfloat16 g_outh[(size_t)BL * DD],   g_outl[(size_t)BL * DD];
static __device__ __align__(256) __nv_bfloat16 g_wwh[(size_t)DD * DD],    g_wwl[(size_t)DD * DD];
static __device__ __align__(256) __nv_bfloat16 g_wrh[(size_t)DD * DD],    g_wrl[(size_t)DD * DD];
static __device__ __align__(256) __nv_bfloat16 g_wkh[(size_t)BL * DD],    g_wkl[(size_t)BL * DD];
static __device__ __align__(256) __nv_bfloat16 g_wkTh[(size_t)BL * DD],   g_wkTl[(size_t)BL * DD];
static __device__ __align__(256) __nv_bfloat16 g_rkgh[(size_t)BL * DD],   g_rkgl[(size_t)BL * DD];
static __device__ __align__(256) __nv_bfloat16 g_vgwTh[(size_t)BL * DD],  g_vgwTl[(size_t)BL * DD];
static __device__ __align__(256) __nv_bfloat16 g_vTh[(size_t)BL * DD],    g_vTl[(size_t)BL * DD];
static __device__ __align__(256) __nv_bfloat16 g_Wsth[(size_t)BB * NM * DD * DD], g_Wstl[(size_t)BB * NM * DD * DD];
static __device__ __align__(256) __nv_bfloat16 g_Ph[(size_t)BB * NM * MC * MC],   g_Pl[(size_t)BB * NM * MC * MC];
static __device__ __align__(256) __nv_bfloat16 g_rdh[(size_t)BL * DD],    g_rdl[(size_t)BL * DD];

// ---- SSD tensor-path operands (512 batches = BB*HH*NC) ----
#define NB (BB * HH * NC)
static __device__ __align__(256) __nv_bfloat16 g_Ch[(size_t)NB * CS * NN],  g_Cl[(size_t)NB * CS * NN];   // C [l][n]
static __device__ __align__(256) __nv_bfloat16 g_Bmh[(size_t)NB * CS * NN], g_Bml[(size_t)NB * CS * NN];  // B [m][n]
static __device__ __align__(256) __nv_bfloat16 g_BTh[(size_t)NB * NN * CS], g_BTl[(size_t)NB * NN * CS];  // B [n][l]
static __device__ __align__(256) __nv_bfloat16 g_vwh[(size_t)NB * HD * CS], g_vwl[(size_t)NB * HD * CS];  // v*ew [d][l]
static __device__ __align__(256) __nv_bfloat16 g_Aph[(size_t)NB * CS * 384], g_Apl[(size_t)NB * CS * 384]; // A' [l][M|Ce]
static __device__ __align__(256) __nv_bfloat16 g_Bph[(size_t)NB * HD * 384], g_Bpl[(size_t)NB * HD * 384]; // B' [d][vT|h]

enum { EPI_STORE = 0, EPI_MASK_SPLIT = 1, EPI_ADD = 2, EPI_FINAL = 3, EPI_STORE_SPLIT = 4, EPI_ADD_SPLIT = 5,
       EPI_SSDMASK = 6, EPI_YGATE = 7 };

// ================= ptx helpers (all plain sm_80+ features) =================
__device__ __forceinline__ uint32_t smem_u32(const void* p) {
    uint32_t a;
    asm("{ .reg .u64 tmp; cvta.to.shared.u64 tmp, %1; cvt.u32.u64 %0, tmp; }" : "=r"(a) : "l"(p));
    return a;
}
__device__ __forceinline__ void cp16(uint32_t dst, const void* src, int ok) {
    int sz = ok ? 16 : 0;
    asm volatile("cp.async.cg.shared.global [%0], [%1], 16, %2;" :: "r"(dst), "l"(src), "r"(sz) : "memory");
}
#define CP_COMMIT() asm volatile("cp.async.commit_group;" ::: "memory")
#define CP_WAIT1()  asm volatile("cp.async.wait_group 1;" ::: "memory")
#define CP_WAIT0()  asm volatile("cp.async.wait_group 0;" ::: "memory")

#define LDM4(r, a) \
    asm volatile("ldmatrix.sync.aligned.m8n8.x4.shared.b16 {%0,%1,%2,%3}, [%4];" \
        : "=r"((r)[0]), "=r"((r)[1]), "=r"((r)[2]), "=r"((r)[3]) : "r"(a))
#define LDM2(r, a) \
    asm volatile("ldmatrix.sync.aligned.m8n8.x2.shared.b16 {%0,%1}, [%2];" \
        : "=r"((r)[0]), "=r"((r)[1]) : "r"(a))
#define MMA16816(c, a, b) \
    asm volatile("mma.sync.aligned.m16n8k16.row.col.f32.bf16.bf16.f32 " \
        "{%0,%1,%2,%3}, {%4,%5,%6,%7}, {%8,%9}, {%0,%1,%2,%3};" \
        : "+f"((c)[0]), "+f"((c)[1]), "+f"((c)[2]), "+f"((c)[3]) \
        : "r"((a)[0]), "r"((a)[1]), "r"((a)[2]), "r"((a)[3]), "r"((b)[0]), "r"((b)[1]))

__device__ __forceinline__ void split2(float v, __nv_bfloat16& h, __nv_bfloat16& l) {
    h = __float2bfloat16(v);
    l = __float2bfloat16(v - __bfloat162float(h));
}

// ================= mma.sync split-bf16 GEMM =================
// C[m,n] = sum_k A[m,k]*B[n,k], via Ahi*Bhi + Ahi*Blo + Alo*Bhi
// block tile 128x128, BK=32, 256 threads (8 warps, 2x4), warp tile 64x32.
// 2-stage cp.async pipeline; supertile rasterization (GROUP_M=16).
#define TILE_B 10240
#define STAGE_B 40960
__global__ void __launch_bounds__(256) tgemm_kernel(
    const __nv_bfloat16* __restrict__ Ahi, const __nv_bfloat16* __restrict__ Alo,
    const __nv_bfloat16* __restrict__ Bhi, const __nv_bfloat16* __restrict__ Blo,
    float* __restrict__ C, __nv_bfloat16* __restrict__ Chi, __nv_bfloat16* __restrict__ Clo,
    int N, int K, long lda, long ldb, long ldc,
    long bsa, long bsb, long bsc,
    int epi, const float* __restrict__ aux1, const float* __restrict__ aux2,
    const float* __restrict__ decayp, float alpha)
{
    extern __shared__ char smem[];
    uint32_t sbase = smem_u32(smem);
    int t = threadIdx.x, lane = t & 31, wid = t >> 5;
    int wm = wid >> 2, wn = wid & 3;

    int bz = blockIdx.z;
    Ahi += (long)bz * bsa; Alo += (long)bz * bsa;
    Bhi += (long)bz * bsb; Blo += (long)bz * bsb;

    // ---- supertile swizzle ----
    int gx = gridDim.x, gy = gridDim.y;
    int pid = blockIdx.y * gx + blockIdx.x;
    const int GM = 16;
    int npg = GM * gx;
    int gid = pid / npg;
    int fm = gid * GM;
    int gsz = min(gy - fm, GM);
    int bm = fm + (pid % gsz);
    int bn = (pid % npg) / gsz;
    long m0 = (long)bm * 128, n0 = (long)bn * 128;

    float acc[4][4][4];
#pragma unroll
    for (int mt = 0; mt < 4; mt++)
#pragma unroll
        for (int nt = 0; nt < 4; nt++)
#pragma unroll
            for (int e = 0; e < 4; e++) acc[mt][nt][e] = 0.f;

    int nk = K >> 5;

    auto load_stage = [&](int s, int ck) {
        long k0 = (long)ck * 32;
        uint32_t sb = sbase + s * STAGE_B;
#pragma unroll
        for (int i = 0; i < 8; i++) {
            int ch = t + i * 256;
            int tile = ch >> 9; int idx = ch & 511; int row = idx >> 2; int part = idx & 3;
            uint32_t dst = sb + tile * TILE_B + row * 80 + part * 16;
            const __nv_bfloat16* srcp;
            int ok = 1;
            if (tile == 0)      srcp = Ahi + (m0 + row) * lda + k0 + part * 8;
            else if (tile == 1) srcp = Alo + (m0 + row) * lda + k0 + part * 8;
            else {
                ok = (n0 + row) < N;
                long r = ok ? (n0 + row) : 0;
                srcp = ((tile == 2) ? Bhi : Blo) + r * ldb + k0 + part * 8;
            }
            cp16(dst, srcp, ok);
        }
        CP_COMMIT();
    };

    load_stage(0, 0);

    for (int ck = 0; ck < nk; ck++) {
        int s = ck & 1;
        if (ck + 1 < nk) { load_stage(s ^ 1, ck + 1); CP_WAIT1(); }
        else CP_WAIT0();
        __syncthreads();

        uint32_t sb = sbase + s * STAGE_B;
        uint32_t a_r = (uint32_t)(wm * 64 + (lane & 15));
        uint32_t a_kb = (uint32_t)((lane >> 4) * 16);
        uint32_t b_r = (uint32_t)(wn * 32 + (lane & 7));
        uint32_t b_kb = (uint32_t)(((lane >> 3) & 1) * 16);
#pragma unroll
        for (int ks = 0; ks < 2; ks++) {
            uint32_t kof = ks * 32;
            uint32_t bh[4][2], bl[4][2];
#pragma unroll
            for (int nt = 0; nt < 4; nt++) {
                uint32_t ab = sb + (b_r + nt * 8) * 80 + kof + b_kb;
                LDM2(bh[nt], ab + 2 * TILE_B);
                LDM2(bl[nt], ab + 3 * TILE_B);
            }
#pragma unroll
            for (int mt = 0; mt < 4; mt++) {
                uint32_t ah[4], al[4];
                uint32_t aa = sb + (a_r + mt * 16) * 80 + kof + a_kb;
                LDM4(ah, aa);
                LDM4(al, aa + TILE_B);
#pragma unroll
                for (int nt = 0; nt < 4; nt++) {
                    MMA16816(acc[mt][nt], ah, bh[nt]);
                    MMA16816(acc[mt][nt], ah, bl[nt]);
                    MMA16816(acc[mt][nt], al, bh[nt]);
                }
            }
        }
        __syncthreads();
    }

    // ---- epilogue ----
    float lg = 0.f;
    if (epi == EPI_MASK_SPLIT) {
        float gamma = 1.f / (1.f + expf(-decayp[0]));
        lg = logf(gamma);
    }
    C += (long)bz * bsc;
    if (Chi) { Chi += (long)bz * bsc; Clo += (long)bz * bsc; }

#pragma unroll
    for (int mt = 0; mt < 4; mt++) {
#pragma unroll
        for (int nt = 0; nt < 4; nt++) {
            long col = n0 + wn * 32 + nt * 8 + (lane & 3) * 2;
            long row0 = m0 + wm * 64 + mt * 16 + (lane >> 2);
#pragma unroll
            for (int e = 0; e < 4; e++) {
                long m = row0 + (e >> 1) * 8;
                long n = col + (e & 1);
                if (n >= N) continue;
                long idx = m * ldc + n;
                float v = acc[mt][nt][e];
                if (epi == EPI_STORE) C[idx] = v;
                else if (epi == EPI_STORE_SPLIT) {
                    C[idx] = v;
                    split2(v, Chi[idx], Clo[idx]);
                } else if (epi == EPI_MASK_SPLIT) {
                    float mv = (m > n) ? v * expf((float)(m - 1 - n) * lg) : 0.f;
                    split2(mv, Chi[idx], Clo[idx]);
                } else if (epi == EPI_ADD) C[idx] += v;
                else if (epi == EPI_ADD_SPLIT) {
                    float r = C[idx] + v;
                    C[idx] = r;
                    split2(r, Chi[idx], Clo[idx]);
                } else if (epi == EPI_SSDMASK) {
                    const float* cumb = decayp + (long)bz * CS;
                    float mv = (m >= n) ? v * expf(cumb[m] - cumb[n]) : 0.f;
                    split2(mv, Chi[idx], Clo[idx]);
                } else if (epi == EPI_YGATE) {
                    int cz = bz % NC; int hz = (bz / NC) % HH; int b2 = bz / (NC * HH);
                    long grow = (long)b2 * LL + (long)cz * CS + m;
                    long vix = grow * (long)DI + hz * HD + n;
                    float vv = g_val[vix];
                    float gg = g_proj[grow * (long)PROJ + DI + hz * HD + n];
                    float yo = (v + aux1[hz * HD + n] * vv) * gg / (1.f + expf(-gg));
                    split2(yo, g_Ygh[vix], g_Ygl[vix]);
                } else C[idx] = aux1[idx] + aux2[idx] + alpha * v;
            }
        }
    }
}

// ================= elementwise / SIMT kernels =================
__global__ void splitk_kernel(const float* __restrict__ src, __nv_bfloat16* __restrict__ h,
                              __nv_bfloat16* __restrict__ l, long n)
{
    long i = (long)blockIdx.x * 256 + threadIdx.x;
    if (i >= n) return;
    split2(src[i], h[i], l[i]);
}

__global__ void rmsnorm_kernel(const float* __restrict__ x, const float* __restrict__ w)
{
    int row = blockIdx.x;
    const float* xr = x + (long)row * DD;
    float s = 0.f;
    for (int i = threadIdx.x; i < DD; i += 256) { float v = xr[i]; s += v * v; }
    __shared__ float red[256];
    red[threadIdx.x] = s; __syncthreads();
    for (int o = 128; o > 0; o >>= 1) {
        if (threadIdx.x < o) red[threadIdx.x] += red[threadIdx.x + o];
        __syncthreads();
    }
    float r = rsqrtf(red[0] / (float)DD + 1e-6f);
    for (int i = threadIdx.x; i < DD; i += 256) {
        float v = xr[i] * r * w[i];
        long idx = (long)row * DD + i;
        split2(v, g_xnh[idx], g_xnl[idx]);
    }
}

__global__ void conv_silu_kernel(const float* __restrict__ cw, const float* __restrict__ cb)
{
    long idx = (long)blockIdx.x * 256 + threadIdx.x;
    if (idx >= (long)BL * DI) return;
    int c = (int)(idx % DI);
    long bl = idx / DI;
    int l = (int)(bl % LL);
    long b = bl / LL;
    float acc = cb[c];
#pragma unroll
    for (int k = 0; k < 4; k++) {
        int ls = l - 3 + k;
        if (ls >= 0) acc += cw[c * 4 + k] * g_proj[(b * LL + ls) * (long)PROJ + c];
    }
    g_val[idx] = acc / (1.f + expf(-acc));
}

__global__ void cum_kernel(const float* __restrict__ dt_bias, const float* __restrict__ A_log)
{
    int bid = blockIdx.x;
    int c = bid % NC; int h = (bid / NC) % HH; int b = bid / (NC * HH);
    int t = threadIdx.x;
    long row = (long)b * LL + c * CS + t;
    float x = g_proj[row * (long)PROJ + 2 * DI + 2 * HH * NN + h] + dt_bias[h];
    float sp = (x > 20.f) ? x : log1pf(expf(x));
    float ld = -expf(A_log[h]) * sp;
    __shared__ float s[256];
    s[t] = ld; __syncthreads();
    for (int o = 1; o < 256; o <<= 1) {
        float v = (t >= o) ? s[t - o] : 0.f;
        __syncthreads();
        s[t] += v;
        __syncthreads();
    }
    g_cum[(long)bid * CS + t] = s[t];
}

// build SSD tensor-path operands: C/Bm row-major splits, BT/vw transposed splits,
// Ce into A'[.,256:384], vT into B'[.,0:256]
__global__ void ssdprep_kernel()
{
    int blk = blockIdx.x;
    int part = blk & 3;
    int bhc = blk >> 2;
    int c = bhc % NC; int h = (bhc / NC) % HH; int b = bhc / (NC * HH);
    const float* cumc = g_cum + (long)bhc * CS;
    float clast = cumc[CS - 1];
    long rowb = (long)b * LL + (long)c * CS;
    int t = threadIdx.x;

    long cbase = (long)bhc * CS * NN;
    long tbase = (long)bhc * NN * CS;
    long abase = (long)bhc * CS * 384;
    long wbase = (long)bhc * HD * CS;
    long pbase = (long)bhc * HD * 384;

    // C/Bm/Ce: n-contiguous
    for (int i = t; i < 64 * 128; i += 256) {
        int l = part * 64 + (i >> 7); int n = i & 127;
        long row = rowb + l;
        float Cv = g_proj[row * (long)PROJ + 2 * DI + HH * NN + h * NN + n];
        float Bv = g_proj[row * (long)PROJ + 2 * DI + h * NN + n];
        split2(Cv, g_Ch[cbase + (long)l * NN + n], g_Cl[cbase + (long)l * NN + n]);
        split2(Bv, g_Bmh[cbase + (long)l * NN + n], g_Bml[cbase + (long)l * NN + n]);
        split2(Cv * expf(cumc[l]), g_Aph[abase + (long)l * 384 + 256 + n],
                                   g_Apl[abase + (long)l * 384 + 256 + n]);
    }
    // BT: l-contiguous writes (reads hit L2)
    for (int i = t; i < 128 * 64; i += 256) {
        int n = i >> 6; int l = part * 64 + (i & 63);
        float Bv = g_proj[(rowb + l) * (long)PROJ + 2 * DI + h * NN + n];
        split2(Bv, g_BTh[tbase + (long)n * CS + l], g_BTl[tbase + (long)n * CS + l]);
    }
    // vT into B' and vw (=v*ew): l-contiguous writes
    for (int i = t; i < 128 * 64; i += 256) {
        int d = i >> 6; int l = part * 64 + (i & 63);
        float vv = g_val[(rowb + l) * (long)DI + h * HD + d];
        split2(vv, g_Bph[pbase + (long)d * 384 + l], g_Bpl[pbase + (long)d * 384 + l]);
        float ew = expf(clast - cumc[l]);
        split2(vv * ew, g_vwh[wbase + (long)d * CS + l], g_vwl[wbase + (long)d * CS + l]);
    }
}

// h-state recurrence; writes h splits into B'[.,256:384]
__global__ void hscan_kernel()
{
    long i = (long)blockIdx.x * 256 + threadIdx.x;
    if (i >= (long)BB * HH * HD * NN) return;
    int dn = (int)(i % (HD * NN));
    int d = dn / NN, n = dn % NN;
    long bh = i / (HD * NN);
    float hcur = 0.f;
    for (int c = 0; c < NC; c++) {
        long bhc = bh * NC + c;
        float Ac = expf(g_cum[bhc * CS + CS - 1]);
        long off = bhc * HD * 384 + (long)d * 384 + 256 + n;
        split2(hcur, g_Bph[off], g_Bpl[off]);
        hcur = Ac * hcur + g_T[bhc * (long)(HD * NN) + dn];
    }
}

// fused memory-module prep
__global__ void memprep_kernel(const float* __restrict__ decayp)
{
    long i = (long)blockIdx.x * 256 + threadIdx.x;
    if (i >= (long)BL * DD) return;
    int d = (int)(i % DD);
    long bl = i / DD;
    int linb = (int)(bl % LL);
    long b = bl / LL;
    int tt = linb % MC, cz = linb / MC;
    float gamma = 1.f / (1.f + expf(-decayp[0]));
    float lg = logf(gamma);
    long dstT = (((long)b * NM + cz) * DD + d) * MC + tt;

    float wkv = (linb == 0) ? 0.f : g_out[i - DD];
    split2(wkv, g_wkh[i], g_wkl[i]);
    split2(wkv, g_wkTh[dstT], g_wkTl[dstT]);

    float rk = g_out[i] * expf((float)tt * lg);
    split2(rk, g_rkgh[i], g_rkgl[i]);

    float vv = g_v[i];
    split2(vv, g_vTh[dstT], g_vTl[dstT]);
    float vgw = vv * expf((float)(MC - 1 - tt) * lg);
    split2(vgw, g_vgwTh[dstT], g_vgwTl[dstT]);
}

__global__ void wscan_kernel(const float* __restrict__ decayp)
{
    long i = (long)blockIdx.x * 256 + threadIdx.x;
    if (i >= (long)BB * DD * DD) return;
    long de = i % ((long)DD * DD);
    long b = i / ((long)DD * DD);
    float gamma = 1.f / (1.f + expf(-decayp[0]));
    float gmc = expf(256.f * logf(gamma));
    float w = 0.f;
    for (int c = 0; c < NM; c++) {
        long off = (b * NM + c) * (long)(DD * DD) + de;
        split2(w, g_Wsth[off], g_Wstl[off]);
        w = gmc * w + g_U[off];
    }
}

// ================= host launcher =================
template <typename T>
static T* symaddr(const void* s)
{
    void* p = nullptr;
    cudaGetSymbolAddress(&p, s);
    return (T*)p;
}

extern "C" void kernel_launch(void* const* d_in, const int* in_sizes, int n_in,
                              void* d_out, int out_size)
{
    const float* x = (const float*)d_in[0];
    const float* norm_w = (const float*)d_in[1];
    const float* w_in = (const float*)d_in[2];
    const float* conv_w = (const float*)d_in[3];
    const float* conv_b = (const float*)d_in[4];
    const float* A_log = (const float*)d_in[5];
    const float* dt_bias = (const float*)d_in[6];
    const float* D_skip = (const float*)d_in[7];
    const float* w_out = (const float*)d_in[8];
    const float* w_write = (const float*)d_in[9];
    const float* w_read = (const float*)d_in[10];
    const float* decay = (const float*)d_in[11];
    float* out = (float*)d_out;

    typedef __nv_bfloat16 bf;
    float* p_proj  = symaddr<float>(g_proj);
    float* p_cum   = symaddr<float>(g_cum);
    float* p_T     = symaddr<float>(g_T);
    float* p_out   = symaddr<float>(g_out);
    float* p_v     = symaddr<float>(g_v);
    float* p_U     = symaddr<float>(g_U);
    float* p_reads = symaddr<float>(g_reads);
    bf *xnh = symaddr<bf>(g_xnh),   *xnl = symaddr<bf>(g_xnl);
    bf *winh = symaddr<bf>(g_winh), *winl = symaddr<bf>(g_winl);
    bf *Ygh = symaddr<bf>(g_Ygh),   *Ygl = symaddr<bf>(g_Ygl);
    bf *woh = symaddr<bf>(g_woh),   *wol = symaddr<bf>(g_wol);
    bf *outh = symaddr<bf>(g_outh), *outl = symaddr<bf>(g_outl);
    bf *wwh = symaddr<bf>(g_wwh),   *wwl = symaddr<bf>(g_wwl);
    bf *wrh = symaddr<bf>(g_wrh),   *wrl = symaddr<bf>(g_wrl);
    bf *wkh = symaddr<bf>(g_wkh),   *wkl = symaddr<bf>(g_wkl);
    bf *wkTh = symaddr<bf>(g_wkTh), *wkTl = symaddr<bf>(g_wkTl);
    bf *rkgh = symaddr<bf>(g_rkgh), *rkgl = symaddr<bf>(g_rkgl);
    bf *vgwTh = symaddr<bf>(g_vgwTh), *vgwTl = symaddr<bf>(g_vgwTl);
    bf *vTh = symaddr<bf>(g_vTh),   *vTl = symaddr<bf>(g_vTl);
    bf *Wsth = symaddr<bf>(g_Wsth), *Wstl = symaddr<bf>(g_Wstl);
    bf *Phh = symaddr<bf>(g_Ph),    *Pll = symaddr<bf>(g_Pl);
    bf *rdh = symaddr<bf>(g_rdh),   *rdl = symaddr<bf>(g_rdl);
    bf *Ch = symaddr<bf>(g_Ch),     *Cl = symaddr<bf>(g_Cl);
    bf *Bmh = symaddr<bf>(g_Bmh),   *Bml = symaddr<bf>(g_Bml);
    bf *BTh = symaddr<bf>(g_BTh),   *BTl = symaddr<bf>(g_BTl);
    bf *vwh = symaddr<bf>(g_vwh),   *vwl = symaddr<bf>(g_vwl);
    bf *Aph = symaddr<bf>(g_Aph),   *Apl = symaddr<bf>(g_Apl);
    bf *Bph = symaddr<bf>(g_Bph),   *Bpl = symaddr<bf>(g_Bpl);

    const int gsmem = 2 * STAGE_B;  // 81920
    cudaFuncSetAttribute(tgemm_kernel, cudaFuncAttributeMaxDynamicSharedMemorySize, gsmem);

    rmsnorm_kernel<<<BL, 256>>>(x, norm_w);

    splitk_kernel<<<(int)(((long)PROJ * DD + 255) / 256), 256>>>(w_in, winh, winl, (long)PROJ * DD);
    splitk_kernel<<<(int)(((long)DD * DI + 255) / 256), 256>>>(w_out, woh, wol, (long)DD * DI);
    splitk_kernel<<<(int)(((long)DD * DD + 255) / 256), 256>>>(w_write, wwh, wwl, (long)DD * DD);
    splitk_kernel<<<(int)(((long)DD * DD + 255) / 256), 256>>>(w_read, wrh, wrl, (long)DD * DD);

    // proj = xn @ w_in^T
    tgemm_kernel<<<dim3((PROJ + 127) / 128, BL / 128, 1), 256, gsmem>>>(
        xnh, xnl, winh, winl, p_proj, nullptr, nullptr,
        PROJ, DD, DD, DD, PROJ, 0, 0, 0, EPI_STORE, nullptr, nullptr, nullptr, 0.f);

    conv_silu_kernel<<<(int)(((long)BL * DI + 255) / 256), 256>>>(conv_w, conv_b);
    cum_kernel<<<BB * HH * NC, 256>>>(dt_bias, A_log);
    ssdprep_kernel<<<NB * 4, 256>>>();

    // S = C @ B^T (K=n), masked -> M splits into A'[:, 0:256]
    tgemm_kernel<<<dim3(2, 2, NB), 256, gsmem>>>(
        Ch, Cl, Bmh, Bml, p_T /*unused*/, Aph, Apl,
        CS, NN, NN, NN, 384,
        (long)CS * NN, (long)CS * NN, (long)CS * 384,
        EPI_SSDMASK, nullptr, nullptr, p_cum, 0.f);

    // T = vw @ B (K=l)
    tgemm_kernel<<<dim3(1, 1, NB), 256, gsmem>>>(
        vwh, vwl, BTh, BTl, p_T, nullptr, nullptr,
        NN, CS, CS, CS, NN,
        (long)HD * CS, (long)NN * CS, (long)HD * NN,
        EPI_STORE, nullptr, nullptr, nullptr, 0.f);

    hscan_kernel<<<(int)(((long)BB * HH * HD * NN + 255) / 256), 256>>>();

    // Y = A'(=[M|Ce]) @ B'(=[vT|h])^T (K=384) -> Yg splits via YGATE epilogue
    tgemm_kernel<<<dim3(1, 2, NB), 256, gsmem>>>(
        Aph, Apl, Bph, Bpl, p_T /*unused*/, nullptr, nullptr,
        HD, 384, 384, 384, HD,
        (long)CS * 384, (long)HD * 384, 0,
        EPI_YGATE, D_skip, nullptr, nullptr, 0.f);

    // out = Yg @ w_out^T
    tgemm_kernel<<<dim3(DD / 128, BL / 128, 1), 256, gsmem>>>(
        Ygh, Ygl, woh, wol, p_out, outh, outl,
        DD, DI, DI, DI, DD, 0, 0, 0, EPI_STORE_SPLIT, nullptr, nullptr, nullptr, 0.f);

    // v = out @ w_write^T
    tgemm_kernel<<<dim3(DD / 128, BL / 128, 1), 256, gsmem>>>(
        outh, outl, wwh, wwl, p_v, nullptr, nullptr,
        DD, DD, DD, DD, DD, 0, 0, 0, EPI_STORE, nullptr, nullptr, nullptr, 0.f);

    memprep_kernel<<<(int)(((long)BL * DD + 255) / 256), 256>>>(decay);

    // U = vgwT @ wkT^T
    tgemm_kernel<<<dim3(DD / 128, DD / 128, BB * NM), 256, gsmem>>>(
        vgwTh, vgwTl, wkTh, wkTl, p_U, nullptr, nullptr,
        DD, MC, MC, MC, DD,
        (long)DD * MC, (long)DD * MC, (long)DD * DD,
        EPI_STORE, nullptr, nullptr, nullptr, 0.f);

    wscan_kernel<<<(int)(((long)BB * DD * DD + 255) / 256), 256>>>(decay);

    // inter: reads = rkg @ Wst^T
    tgemm_kernel<<<dim3(DD / 128, MC / 128, BB * NM), 256, gsmem>>>(
        rkgh, rkgl, Wsth, Wstl, p_reads, nullptr, nullptr,
        DD, DD, DD, DD, DD,
        (long)MC * DD, (long)DD * DD, (long)MC * DD,
        EPI_STORE, nullptr, nullptr, nullptr, 0.f);

    // P = (out @ wk^T) * Mmem -> split
    tgemm_kernel<<<dim3(MC / 128, MC / 128, BB * NM), 256, gsmem>>>(
        outh, outl, wkh, wkl, p_reads /*unused*/, Phh, Pll,
        MC, DD, DD, DD, MC,
        (long)MC * DD, (long)MC * DD, (long)MC * MC,
        EPI_MASK_SPLIT, nullptr, nullptr, decay, 0.f);

    // reads += P @ v
    tgemm_kernel<<<dim3(DD / 128, MC / 128, BB * NM), 256, gsmem>>>(
        Phh, Pll, vTh, vTl, p_reads, rdh, rdl,
        DD, MC, MC, MC, DD,
        (long)MC * MC, (long)DD * MC, (long)MC * DD,
        EPI_ADD_SPLIT, nullptr, nullptr, nullptr, 0.f);

    // final = x + out + 0.5 * reads @ w_read^T
    tgemm_kernel<<<dim3(DD / 128, BL / 128, 1), 256, gsmem>>>(
        rdh, rdl, wrh, wrl, out, nullptr, nullptr,
        DD, DD, DD, DD, DD, 0, 0, 0,
        EPI_FINAL, x, p_out, nullptr, ALPHA);
}

// round 17
// speedup vs baseline: 1.6858x; 1.0241x over previous
#include <cuda_runtime.h>
#include <cuda_bf16.h>
#include <math.h>
#include <stdint.h>

#define BB 2
#define LL 4096
#define DD 1024
#define DI 2048
#define HH 16
#define HD 128
#define NN 128
#define CS 256
#define NC 16
#define MC 256
#define NM 16
#define PROJ 8208
#define BL 8192
#define ALPHA 0.5f

// ================= fp32 scratch =================
static __device__ __align__(256) float g_proj[(size_t)BL * PROJ];
static __device__ __align__(256) float g_val[(size_t)BL * DI];
static __device__ __align__(256) float g_cum[(size_t)BB * HH * NC * CS];
static __device__ __align__(256) float g_T[(size_t)BB * HH * NC * HD * NN];
static __device__ __align__(256) float g_out[(size_t)BL * DD];
static __device__ __align__(256) float g_v[(size_t)BL * DD];
static __device__ __align__(256) float g_U[(size_t)BB * NM * DD * DD];
static __device__ __align__(256) float g_reads[(size_t)BL * DD];

// ================= bf16 split scratch =================
static __device__ __align__(256) __nv_bfloat16 g_xnh[(size_t)BL * DD],    g_xnl[(size_t)BL * DD];
static __device__ __align__(256) __nv_bfloat16 g_winh[(size_t)PROJ * DD], g_winl[(size_t)PROJ * DD];
static __device__ __align__(256) __nv_bfloat16 g_Ygh[(size_t)BL * DI],    g_Ygl[(size_t)BL * DI];
static __device__ __align__(256) __nv_bfloat16 g_woh[(size_t)DD * DI],    g_wol[(size_t)DD * DI];
static __device__ __align__(256) __nv_bfloat16 g_outh[(size_t)BL * DD],   g_outl[(size_t)BL * DD];
static __device__ __align__(256) __nv_bfloat16 g_wwh[(size_t)DD * DD],    g_wwl[(size_t)DD * DD];
static __device__ __align__(256) __nv_bfloat16 g_wrh[(size_t)DD * DD],    g_wrl[(size_t)DD * DD];
static __device__ __align__(256) __nv_bfloat16 g_wkh[(size_t)BL * DD],    g_wkl[(size_t)BL * DD];
static __device__ __align__(256) __nv_bfloat16 g_wkTh[(size_t)BL * DD],   g_wkTl[(size_t)BL * DD];
static __device__ __align__(256) __nv_bfloat16 g_rkgh[(size_t)BL * DD],   g_rkgl[(size_t)BL * DD];
static __device__ __align__(256) __nv_bfloat16 g_vgwTh[(size_t)BL * DD],  g_vgwTl[(size_t)BL * DD];
static __device__ __align__(256) __nv_bfloat16 g_vTh[(size_t)BL * DD],    g_vTl[(size_t)BL * DD];
static __device__ __align__(256) __nv_bfloat16 g_Wsth[(size_t)BB * NM * DD * DD], g_Wstl[(size_t)BB * NM * DD * DD];
static __device__ __align__(256) __nv_bfloat16 g_Ph[(size_t)BB * NM * MC * MC],   g_Pl[(size_t)BB * NM * MC * MC];
static __device__ __align__(256) __nv_bfloat16 g_rdh[(size_t)BL * DD],    g_rdl[(size_t)BL * DD];

// ---- SSD tensor-path operands (512 batches = BB*HH*NC) ----
#define NB (BB * HH * NC)
static __device__ __align__(256) __nv_bfloat16 g_Ch[(size_t)NB * CS * NN],  g_Cl[(size_t)NB * CS * NN];
static __device__ __align__(256) __nv_bfloat16 g_Bmh[(size_t)NB * CS * NN], g_Bml[(size_t)NB * CS * NN];
static __device__ __align__(256) __nv_bfloat16 g_BTh[(size_t)NB * NN * CS], g_BTl[(size_t)NB * NN * CS];
static __device__ __align__(256) __nv_bfloat16 g_vwh[(size_t)NB * HD * CS], g_vwl[(size_t)NB * HD * CS];
static __device__ __align__(256) __nv_bfloat16 g_Aph[(size_t)NB * CS * 384], g_Apl[(size_t)NB * CS * 384];
static __device__ __align__(256) __nv_bfloat16 g_Bph[(size_t)NB * HD * 384], g_Bpl[(size_t)NB * HD * 384];

enum { EPI_STORE = 0, EPI_MASK_SPLIT = 1, EPI_ADD = 2, EPI_FINAL = 3, EPI_STORE_SPLIT = 4, EPI_ADD_SPLIT = 5,
       EPI_SSDMASK = 6, EPI_YGATE = 7 };

// ================= ptx helpers =================
__device__ __forceinline__ uint32_t smem_u32(const void* p) {
    uint32_t a;
    asm("{ .reg .u64 tmp; cvta.to.shared.u64 tmp, %1; cvt.u32.u64 %0, tmp; }" : "=r"(a) : "l"(p));
    return a;
}
__device__ __forceinline__ void cp16(uint32_t dst, const void* src, int ok) {
    int sz = ok ? 16 : 0;
    asm volatile("cp.async.cg.shared.global [%0], [%1], 16, %2;" :: "r"(dst), "l"(src), "r"(sz) : "memory");
}
#define CP_COMMIT() asm volatile("cp.async.commit_group;" ::: "memory")
#define CP_WAIT1()  asm volatile("cp.async.wait_group 1;" ::: "memory")
#define CP_WAIT0()  asm volatile("cp.async.wait_group 0;" ::: "memory")

#define LDM4(r, a) \
    asm volatile("ldmatrix.sync.aligned.m8n8.x4.shared.b16 {%0,%1,%2,%3}, [%4];" \
        : "=r"((r)[0]), "=r"((r)[1]), "=r"((r)[2]), "=r"((r)[3]) : "r"(a))
#define MMA16816(c, a, b) \
    asm volatile("mma.sync.aligned.m16n8k16.row.col.f32.bf16.bf16.f32 " \
        "{%0,%1,%2,%3}, {%4,%5,%6,%7}, {%8,%9}, {%0,%1,%2,%3};" \
        : "+f"((c)[0]), "+f"((c)[1]), "+f"((c)[2]), "+f"((c)[3]) \
        : "r"((a)[0]), "r"((a)[1]), "r"((a)[2]), "r"((a)[3]), "r"((b)[0]), "r"((b)[1]))

__device__ __forceinline__ void split2(float v, __nv_bfloat16& h, __nv_bfloat16& l) {
    h = __float2bfloat16(v);
    l = __float2bfloat16(v - __bfloat162float(h));
}
__device__ __forceinline__ uint16_t bfbits(__nv_bfloat16 v) {
    uint16_t b; memcpy(&b, &v, 2); return b;
}

// ================= mma.sync split-bf16 GEMM =================
#define TILE_B 10240
#define STAGE_B 40960
__global__ void __launch_bounds__(256) tgemm_kernel(
    const __nv_bfloat16* __restrict__ Ahi, const __nv_bfloat16* __restrict__ Alo,
    const __nv_bfloat16* __restrict__ Bhi, const __nv_bfloat16* __restrict__ Blo,
    float* __restrict__ C, __nv_bfloat16* __restrict__ Chi, __nv_bfloat16* __restrict__ Clo,
    int N, int K, long lda, long ldb, long ldc,
    long bsa, long bsb, long bsc,
    int epi, const float* __restrict__ aux1, const float* __restrict__ aux2,
    const float* __restrict__ decayp, float alpha)
{
    extern __shared__ char smem[];
    uint32_t sbase = smem_u32(smem);
    int t = threadIdx.x, lane = t & 31, wid = t >> 5;
    int wm = wid >> 2, wn = wid & 3;

    int bz = blockIdx.z;
    Ahi += (long)bz * bsa; Alo += (long)bz * bsa;
    Bhi += (long)bz * bsb; Blo += (long)bz * bsb;

    // ---- supertile swizzle ----
    int gx = gridDim.x, gy = gridDim.y;
    int pid = blockIdx.y * gx + blockIdx.x;
    const int GM = 16;
    int npg = GM * gx;
    int gid = pid / npg;
    int fm = gid * GM;
    int gsz = min(gy - fm, GM);
    int bm = fm + (pid % gsz);
    int bn = (pid % npg) / gsz;
    long m0 = (long)bm * 128, n0 = (long)bn * 128;

    float acc[4][4][4];
#pragma unroll
    for (int mt = 0; mt < 4; mt++)
#pragma unroll
        for (int nt = 0; nt < 4; nt++)
#pragma unroll
            for (int e = 0; e < 4; e++) acc[mt][nt][e] = 0.f;

    int nk = K >> 5;

    auto load_stage = [&](int s, int ck) {
        long k0 = (long)ck * 32;
        uint32_t sb = sbase + s * STAGE_B;
#pragma unroll
        for (int i = 0; i < 8; i++) {
            int ch = t + i * 256;
            int tile = ch >> 9; int idx = ch & 511; int row = idx >> 2; int part = idx & 3;
            uint32_t dst = sb + tile * TILE_B + row * 80 + part * 16;
            const __nv_bfloat16* srcp;
            int ok = 1;
            if (tile == 0)      srcp = Ahi + (m0 + row) * lda + k0 + part * 8;
            else if (tile == 1) srcp = Alo + (m0 + row) * lda + k0 + part * 8;
            else {
                ok = (n0 + row) < N;
                long r = ok ? (n0 + row) : 0;
                srcp = ((tile == 2) ? Bhi : Blo) + r * ldb + k0 + part * 8;
            }
            cp16(dst, srcp, ok);
        }
        CP_COMMIT();
    };

    load_stage(0, 0);

    // fragment addressing (hoisted)
    uint32_t a_r = (uint32_t)(wm * 64 + (lane & 15));
    uint32_t a_kb = (uint32_t)((lane >> 4) * 16);
    // paired-B x4: lane-group g=lane>>3: (g>>1) -> nt offset within pair, (g&1) -> k-half
    uint32_t b_r4 = (uint32_t)(wn * 32 + ((lane >> 4) << 3) + (lane & 7));
    uint32_t b_kb4 = (uint32_t)(((lane >> 3) & 1) * 16);

    for (int ck = 0; ck < nk; ck++) {
        int s = ck & 1;
        if (ck + 1 < nk) { load_stage(s ^ 1, ck + 1); CP_WAIT1(); }
        else CP_WAIT0();
        __syncthreads();

        uint32_t sb = sbase + s * STAGE_B;
#pragma unroll
        for (int ks = 0; ks < 2; ks++) {
            uint32_t kof = ks * 32;
            uint32_t bh[4][2], bl[4][2];
#pragma unroll
            for (int np = 0; np < 2; np++) {
                uint32_t ab = sb + (b_r4 + np * 16) * 80 + kof + b_kb4;
                uint32_t r4[4];
                LDM4(r4, ab + 2 * TILE_B);
                bh[np * 2][0] = r4[0]; bh[np * 2][1] = r4[1];
                bh[np * 2 + 1][0] = r4[2]; bh[np * 2 + 1][1] = r4[3];
                LDM4(r4, ab + 3 * TILE_B);
                bl[np * 2][0] = r4[0]; bl[np * 2][1] = r4[1];
                bl[np * 2 + 1][0] = r4[2]; bl[np * 2 + 1][1] = r4[3];
            }
#pragma unroll
            for (int mt = 0; mt < 4; mt++) {
                uint32_t ah[4], al[4];
                uint32_t aa = sb + (a_r + mt * 16) * 80 + kof + a_kb;
                LDM4(ah, aa);
                LDM4(al, aa + TILE_B);
#pragma unroll
                for (int nt = 0; nt < 4; nt++) {
                    MMA16816(acc[mt][nt], ah, bh[nt]);
                    MMA16816(acc[mt][nt], ah, bl[nt]);
                    MMA16816(acc[mt][nt], al, bh[nt]);
                }
            }
        }
        __syncthreads();
    }

    // ---- epilogue ----
    float lg = 0.f;
    if (epi == EPI_MASK_SPLIT) {
        float gamma = 1.f / (1.f + expf(-decayp[0]));
        lg = logf(gamma);
    }
    C += (long)bz * bsc;
    if (Chi) { Chi += (long)bz * bsc; Clo += (long)bz * bsc; }

#pragma unroll
    for (int mt = 0; mt < 4; mt++) {
#pragma unroll
        for (int nt = 0; nt < 4; nt++) {
            long col = n0 + wn * 32 + nt * 8 + (lane & 3) * 2;
            long row0 = m0 + wm * 64 + mt * 16 + (lane >> 2);
#pragma unroll
            for (int e = 0; e < 4; e++) {
                long m = row0 + (e >> 1) * 8;
                long n = col + (e & 1);
                if (n >= N) continue;
                long idx = m * ldc + n;
                float v = acc[mt][nt][e];
                if (epi == EPI_STORE) C[idx] = v;
                else if (epi == EPI_STORE_SPLIT) {
                    C[idx] = v;
                    split2(v, Chi[idx], Clo[idx]);
                } else if (epi == EPI_MASK_SPLIT) {
                    float mv = (m > n) ? v * expf((float)(m - 1 - n) * lg) : 0.f;
                    split2(mv, Chi[idx], Clo[idx]);
                } else if (epi == EPI_ADD) C[idx] += v;
                else if (epi == EPI_ADD_SPLIT) {
                    float r = C[idx] + v;
                    C[idx] = r;
                    split2(r, Chi[idx], Clo[idx]);
                } else if (epi == EPI_SSDMASK) {
                    const float* cumb = decayp + (long)bz * CS;
                    float mv = (m >= n) ? v * expf(cumb[m] - cumb[n]) : 0.f;
                    split2(mv, Chi[idx], Clo[idx]);
                } else if (epi == EPI_YGATE) {
                    int cz = bz % NC; int hz = (bz / NC) % HH; int b2 = bz / (NC * HH);
                    long grow = (long)b2 * LL + (long)cz * CS + m;
                    long vix = grow * (long)DI + hz * HD + n;
                    float vv = g_val[vix];
                    float gg = g_proj[grow * (long)PROJ + DI + hz * HD + n];
                    float yo = (v + aux1[hz * HD + n] * vv) * gg / (1.f + expf(-gg));
                    split2(yo, g_Ygh[vix], g_Ygl[vix]);
                } else C[idx] = aux1[idx] + aux2[idx] + alpha * v;
            }
        }
    }
}

// ================= elementwise / SIMT kernels =================
// vectorized: 4 floats -> packed 2x bf16x2 (element count must be /4)
__global__ void splitk_kernel(const float4* __restrict__ src, uint2* __restrict__ h,
                              uint2* __restrict__ l, long n4)
{
    long i = (long)blockIdx.x * 256 + threadIdx.x;
    if (i >= n4) return;
    float4 v = src[i];
    __nv_bfloat16 h0, l0, h1, l1, h2, l2, h3, l3;
    split2(v.x, h0, l0); split2(v.y, h1, l1);
    split2(v.z, h2, l2); split2(v.w, h3, l3);
    uint2 hp, lp;
    hp.x = (uint32_t)bfbits(h0) | ((uint32_t)bfbits(h1) << 16);
    hp.y = (uint32_t)bfbits(h2) | ((uint32_t)bfbits(h3) << 16);
    lp.x = (uint32_t)bfbits(l0) | ((uint32_t)bfbits(l1) << 16);
    lp.y = (uint32_t)bfbits(l2) | ((uint32_t)bfbits(l3) << 16);
    h[i] = hp; l[i] = lp;
}

__global__ void rmsnorm_kernel(const float* __restrict__ x, const float* __restrict__ w)
{
    int row = blockIdx.x;
    const float* xr = x + (long)row * DD;
    float s = 0.f;
    for (int i = threadIdx.x; i < DD; i += 256) { float v = xr[i]; s += v * v; }
    __shared__ float red[256];
    red[threadIdx.x] = s; __syncthreads();
    for (int o = 128; o > 0; o >>= 1) {
        if (threadIdx.x < o) red[threadIdx.x] += red[threadIdx.x + o];
        __syncthreads();
    }
    float r = rsqrtf(red[0] / (float)DD + 1e-6f);
    for (int i = threadIdx.x; i < DD; i += 256) {
        float v = xr[i] * r * w[i];
        long idx = (long)row * DD + i;
        split2(v, g_xnh[idx], g_xnl[idx]);
    }
}

// ===== fused SSD front-end: conv+silu, dt-scan, all prep splits =====
// grid NB*4 (block = (bhc, part)); part owns l in [part*64, part*64+64)
__global__ void __launch_bounds__(256) ssdfused_kernel(
    const float* __restrict__ cw, const float* __restrict__ cb,
    const float* __restrict__ dt_bias, const float* __restrict__ A_log)
{
    __shared__ float scan[CS];
    __shared__ float vsl[64 * 129];
    int blk = blockIdx.x;
    int part = blk & 3;
    int bhc = blk >> 2;
    int c = bhc % NC; int h = (bhc / NC) % HH; int b = bhc / (NC * HH);
    long rowb = (long)b * LL + (long)c * CS;
    int t = threadIdx.x;

    // --- dt-scan (full chunk, redundant per part) ---
    {
        float x = g_proj[(rowb + t) * (long)PROJ + 2 * DI + 2 * HH * NN + h] + dt_bias[h];
        float sp = (x > 20.f) ? x : log1pf(expf(x));
        float ld = -expf(A_log[h]) * sp;
        scan[t] = ld; __syncthreads();
        for (int o = 1; o < 256; o <<= 1) {
            float v = (t >= o) ? scan[t - o] : 0.f;
            __syncthreads();
            scan[t] += v;
            __syncthreads();
        }
        if (part == 0) g_cum[(long)bhc * CS + t] = scan[t];
    }

    long cbase = (long)bhc * CS * NN;
    long tbase = (long)bhc * NN * CS;
    long abase = (long)bhc * CS * 384;
    long wbase = (long)bhc * HD * CS;
    long pbase = (long)bhc * HD * 384;

    // --- conv + silu into smem + g_val ---
    for (int i = t; i < 64 * 128; i += 256) {
        int ll = i >> 7; int d = i & 127;
        int l = part * 64 + ll;
        int c0 = h * HD + d;
        int linb = c * CS + l;
        float acc = cb[c0];
#pragma unroll
        for (int k = 0; k < 4; k++) {
            int ls = linb - 3 + k;
            if (ls >= 0) acc += cw[c0 * 4 + k] * g_proj[((long)b * LL + ls) * (long)PROJ + c0];
        }
        float sv = acc / (1.f + expf(-acc));
        g_val[(rowb + l) * (long)DI + c0] = sv;
        vsl[ll * 129 + d] = sv;
    }
    __syncthreads();

    float clast = scan[CS - 1];

    // --- vT into B'[0:256] and vw (transposed, l-contiguous writes) ---
    for (int i = t; i < 128 * 64; i += 256) {
        int d = i >> 6; int ll = i & 63;
        int l = part * 64 + ll;
        float vv = vsl[ll * 129 + d];
        split2(vv, g_Bph[pbase + (long)d * 384 + l], g_Bpl[pbase + (long)d * 384 + l]);
        float ew = expf(clast - scan[l]);
        split2(vv * ew, g_vwh[wbase + (long)d * CS + l], g_vwl[wbase + (long)d * CS + l]);
    }

    // --- C/Bm/Ce (n-contiguous) ---
    for (int i = t; i < 64 * 128; i += 256) {
        int l = part * 64 + (i >> 7); int n = i & 127;
        long row = rowb + l;
        float Cv = g_proj[row * (long)PROJ + 2 * DI + HH * NN + h * NN + n];
        float Bv = g_proj[row * (long)PROJ + 2 * DI + h * NN + n];
        split2(Cv, g_Ch[cbase + (long)l * NN + n], g_Cl[cbase + (long)l * NN + n]);
        split2(Bv, g_Bmh[cbase + (long)l * NN + n], g_Bml[cbase + (long)l * NN + n]);
        split2(Cv * expf(scan[l]), g_Aph[abase + (long)l * 384 + 256 + n],
                                   g_Apl[abase + (long)l * 384 + 256 + n]);
    }
    // --- BT (l-contiguous writes) ---
    for (int i = t; i < 128 * 64; i += 256) {
        int n = i >> 6; int l = part * 64 + (i & 63);
        float Bv = g_proj[(rowb + l) * (long)PROJ + 2 * DI + h * NN + n];
        split2(Bv, g_BTh[tbase + (long)n * CS + l], g_BTl[tbase + (long)n * CS + l]);
    }
}

// h-state recurrence; writes h splits into B'[.,256:384]
__global__ void hscan_kernel()
{
    long i = (long)blockIdx.x * 256 + threadIdx.x;
    if (i >= (long)BB * HH * HD * NN) return;
    int dn = (int)(i % (HD * NN));
    int d = dn / NN, n = dn % NN;
    long bh = i / (HD * NN);
    float hcur = 0.f;
    for (int c = 0; c < NC; c++) {
        long bhc = bh * NC + c;
        float Ac = expf(g_cum[bhc * CS + CS - 1]);
        long off = bhc * HD * 384 + (long)d * 384 + 256 + n;
        split2(hcur, g_Bph[off], g_Bpl[off]);
        hcur = Ac * hcur + g_T[bhc * (long)(HD * NN) + dn];
    }
}

__global__ void memprep_kernel(const float* __restrict__ decayp)
{
    long i = (long)blockIdx.x * 256 + threadIdx.x;
    if (i >= (long)BL * DD) return;
    int d = (int)(i % DD);
    long bl = i / DD;
    int linb = (int)(bl % LL);
    long b = bl / LL;
    int tt = linb % MC, cz = linb / MC;
    float gamma = 1.f / (1.f + expf(-decayp[0]));
    float lg = logf(gamma);
    long dstT = (((long)b * NM + cz) * DD + d) * MC + tt;

    float wkv = (linb == 0) ? 0.f : g_out[i - DD];
    split2(wkv, g_wkh[i], g_wkl[i]);
    split2(wkv, g_wkTh[dstT], g_wkTl[dstT]);

    float rk = g_out[i] * expf((float)tt * lg);
    split2(rk, g_rkgh[i], g_rkgl[i]);

    float vv = g_v[i];
    split2(vv, g_vTh[dstT], g_vTl[dstT]);
    float vgw = vv * expf((float)(MC - 1 - tt) * lg);
    split2(vgw, g_vgwTh[dstT], g_vgwTl[dstT]);
}

__global__ void wscan_kernel(const float* __restrict__ decayp)
{
    long i = (long)blockIdx.x * 256 + threadIdx.x;
    if (i >= (long)BB * DD * DD) return;
    long de = i % ((long)DD * DD);
    long b = i / ((long)DD * DD);
    float gamma = 1.f / (1.f + expf(-decayp[0]));
    float gmc = expf(256.f * logf(gamma));
    float w = 0.f;
    for (int c = 0; c < NM; c++) {
        long off = (b * NM + c) * (long)(DD * DD) + de;
        split2(w, g_Wsth[off], g_Wstl[off]);
        w = gmc * w + g_U[off];
    }
}

// ================= host launcher =================
template <typename T>
static T* symaddr(const void* s)
{
    void* p = nullptr;
    cudaGetSymbolAddress(&p, s);
    return (T*)p;
}

extern "C" void kernel_launch(void* const* d_in, const int* in_sizes, int n_in,
                              void* d_out, int out_size)
{
    const float* x = (const float*)d_in[0];
    const float* norm_w = (const float*)d_in[1];
    const float* w_in = (const float*)d_in[2];
    const float* conv_w = (const float*)d_in[3];
    const float* conv_b = (const float*)d_in[4];
    const float* A_log = (const float*)d_in[5];
    const float* dt_bias = (const float*)d_in[6];
    const float* D_skip = (const float*)d_in[7];
    const float* w_out = (const float*)d_in[8];
    const float* w_write = (const float*)d_in[9];
    const float* w_read = (const float*)d_in[10];
    const float* decay = (const float*)d_in[11];
    float* out = (float*)d_out;

    typedef __nv_bfloat16 bf;
    float* p_proj  = symaddr<float>(g_proj);
    float* p_cum   = symaddr<float>(g_cum);
    float* p_T     = symaddr<float>(g_T);
    float* p_out   = symaddr<float>(g_out);
    float* p_v     = symaddr<float>(g_v);
    float* p_U     = symaddr<float>(g_U);
    float* p_reads = symaddr<float>(g_reads);
    bf *xnh = symaddr<bf>(g_xnh),   *xnl = symaddr<bf>(g_xnl);
    bf *winh = symaddr<bf>(g_winh), *winl = symaddr<bf>(g_winl);
    bf *Ygh = symaddr<bf>(g_Ygh),   *Ygl = symaddr<bf>(g_Ygl);
    bf *woh = symaddr<bf>(g_woh),   *wol = symaddr<bf>(g_wol);
    bf *outh = symaddr<bf>(g_outh), *outl = symaddr<bf>(g_outl);
    bf *wwh = symaddr<bf>(g_wwh),   *wwl = symaddr<bf>(g_wwl);
    bf *wrh = symaddr<bf>(g_wrh),   *wrl = symaddr<bf>(g_wrl);
    bf *wkh = symaddr<bf>(g_wkh),   *wkl = symaddr<bf>(g_wkl);
    bf *wkTh = symaddr<bf>(g_wkTh), *wkTl = symaddr<bf>(g_wkTl);
    bf *rkgh = symaddr<bf>(g_rkgh), *rkgl = symaddr<bf>(g_rkgl);
    bf *vgwTh = symaddr<bf>(g_vgwTh), *vgwTl = symaddr<bf>(g_vgwTl);
    bf *vTh = symaddr<bf>(g_vTh),   *vTl = symaddr<bf>(g_vTl);
    bf *Wsth = symaddr<bf>(g_Wsth), *Wstl = symaddr<bf>(g_Wstl);
    bf *Phh = symaddr<bf>(g_Ph),    *Pll = symaddr<bf>(g_Pl);
    bf *rdh = symaddr<bf>(g_rdh),   *rdl = symaddr<bf>(g_rdl);
    bf *Ch = symaddr<bf>(g_Ch),     *Cl = symaddr<bf>(g_Cl);
    bf *Bmh = symaddr<bf>(g_Bmh),   *Bml = symaddr<bf>(g_Bml);
    bf *BTh = symaddr<bf>(g_BTh),   *BTl = symaddr<bf>(g_BTl);
    bf *vwh = symaddr<bf>(g_vwh),   *vwl = symaddr<bf>(g_vwl);
    bf *Aph = symaddr<bf>(g_Aph),   *Apl = symaddr<bf>(g_Apl);
    bf *Bph = symaddr<bf>(g_Bph),   *Bpl = symaddr<bf>(g_Bpl);

    const int gsmem = 2 * STAGE_B;  // 81920
    cudaFuncSetAttribute(tgemm_kernel, cudaFuncAttributeMaxDynamicSharedMemorySize, gsmem);

    rmsnorm_kernel<<<BL, 256>>>(x, norm_w);

    splitk_kernel<<<(int)(((long)PROJ * DD / 4 + 255) / 256), 256>>>(
        (const float4*)w_in, (uint2*)winh, (uint2*)winl, (long)PROJ * DD / 4);
    splitk_kernel<<<(int)(((long)DD * DI / 4 + 255) / 256), 256>>>(
        (const float4*)w_out, (uint2*)woh, (uint2*)wol, (long)DD * DI / 4);
    splitk_kernel<<<(int)(((long)DD * DD / 4 + 255) / 256), 256>>>(
        (const float4*)w_write, (uint2*)wwh, (uint2*)wwl, (long)DD * DD / 4);
    splitk_kernel<<<(int)(((long)DD * DD / 4 + 255) / 256), 256>>>(
        (const float4*)w_read, (uint2*)wrh, (uint2*)wrl, (long)DD * DD / 4);

    // proj = xn @ w_in^T
    tgemm_kernel<<<dim3((PROJ + 127) / 128, BL / 128, 1), 256, gsmem>>>(
        xnh, xnl, winh, winl, p_proj, nullptr, nullptr,
        PROJ, DD, DD, DD, PROJ, 0, 0, 0, EPI_STORE, nullptr, nullptr, nullptr, 0.f);

    // fused conv+silu + dt-scan + prep splits
    ssdfused_kernel<<<NB * 4, 256>>>(conv_w, conv_b, dt_bias, A_log);

    // S = C @ B^T, masked -> M splits into A'[:, 0:256]
    tgemm_kernel<<<dim3(2, 2, NB), 256, gsmem>>>(
        Ch, Cl, Bmh, Bml, p_T /*unused*/, Aph, Apl,
        CS, NN, NN, NN, 384,
        (long)CS * NN, (long)CS * NN, (long)CS * 384,
        EPI_SSDMASK, nullptr, nullptr, p_cum, 0.f);

    // T = vw @ B
    tgemm_kernel<<<dim3(1, 1, NB), 256, gsmem>>>(
        vwh, vwl, BTh, BTl, p_T, nullptr, nullptr,
        NN, CS, CS, CS, NN,
        (long)HD * CS, (long)NN * CS, (long)HD * NN,
        EPI_STORE, nullptr, nullptr, nullptr, 0.f);

    hscan_kernel<<<(int)(((long)BB * HH * HD * NN + 255) / 256), 256>>>();

    // Y = A' @ B'^T (K=384) -> Yg splits via YGATE epilogue
    tgemm_kernel<<<dim3(1, 2, NB), 256, gsmem>>>(
        Aph, Apl, Bph, Bpl, p_T /*unused*/, nullptr, nullptr,
        HD, 384, 384, 384, HD,
        (long)CS * 384, (long)HD * 384, 0,
        EPI_YGATE, D_skip, nullptr, nullptr, 0.f);

    // out = Yg @ w_out^T
    tgemm_kernel<<<dim3(DD / 128, BL / 128, 1), 256, gsmem>>>(
        Ygh, Ygl, woh, wol, p_out, outh, outl,
        DD, DI, DI, DI, DD, 0, 0, 0, EPI_STORE_SPLIT, nullptr, nullptr, nullptr, 0.f);

    // v = out @ w_write^T
    tgemm_kernel<<<dim3(DD / 128, BL / 128, 1), 256, gsmem>>>(
        outh, outl, wwh, wwl, p_v, nullptr, nullptr,
        DD, DD, DD, DD, DD, 0, 0, 0, EPI_STORE, nullptr, nullptr, nullptr, 0.f);

    memprep_kernel<<<(int)(((long)BL * DD + 255) / 256), 256>>>(decay);

    // U = vgwT @ wkT^T
    tgemm_kernel<<<dim3(DD / 128, DD / 128, BB * NM), 256, gsmem>>>(
        vgwTh, vgwTl, wkTh, wkTl, p_U, nullptr, nullptr,
        DD, MC, MC, MC, DD,
        (long)DD * MC, (long)DD * MC, (long)DD * DD,
        EPI_STORE, nullptr, nullptr, nullptr, 0.f);

    wscan_kernel<<<(int)(((long)BB * DD * DD + 255) / 256), 256>>>(decay);

    // inter: reads = rkg @ Wst^T
    tgemm_kernel<<<dim3(DD / 128, MC / 128, BB * NM), 256, gsmem>>>(
        rkgh, rkgl, Wsth, Wstl, p_reads, nullptr, nullptr,
        DD, DD, DD, DD, DD,
        (long)MC * DD, (long)DD * DD, (long)MC * DD,
        EPI_STORE, nullptr, nullptr, nullptr, 0.f);

    // P = (out @ wk^T) * Mmem -> split
    tgemm_kernel<<<dim3(MC / 128, MC / 128, BB * NM), 256, gsmem>>>(
        outh, outl, wkh, wkl, p_reads /*unused*/, Phh, Pll,
        MC, DD, DD, DD, MC,
        (long)MC * DD, (long)MC * DD, (long)MC * MC,
        EPI_MASK_SPLIT, nullptr, nullptr, decay, 0.f);

    // reads += P @ v
    tgemm_kernel<<<dim3(DD / 128, MC / 128, BB * NM), 256, gsmem>>>(
        Phh, Pll, vTh, vTl, p_reads, rdh, rdl,
        DD, MC, MC, MC, DD,
        (long)MC * MC, (long)DD * MC, (long)MC * DD,
        EPI_ADD_SPLIT, nullptr, nullptr, nullptr, 0.f);

    // final = x + out + 0.5 * reads @ w_read^T
    tgemm_kernel<<<dim3(DD / 128, BL / 128, 1), 256, gsmem>>>(
        rdh, rdl, wrh, wrl, out, nullptr, nullptr,
        DD, DD, DD, DD, DD, 0, 0, 0,
        EPI_FINAL, x, p_out, nullptr, ALPHA);
}